// round 2
// baseline (speedup 1.0000x reference)
#include <cuda_runtime.h>
#include <math.h>

// Problem constants
#define BB 8
#define SS 2048
#define DD 512
#define UU 512

// Scratch for Q/K/V projections (32 MB each) — device globals, no allocation.
__device__ float g_q[(size_t)BB * SS * UU];
__device__ float g_k[(size_t)BB * SS * UU];
__device__ float g_v[(size_t)BB * SS * UU];

// ---------------------------------------------------------------------------
// Generic 128x128 tile SGEMM body. 256 threads, BK=8, 8x8 per-thread microtile.
// A is MxK row-major (lda), B is KxN row-major (ldb) or, when TRANSB, B is the
// NxK row-major matrix whose transpose we multiply (ldb = its row stride).
// C tile at (blockIdx.y*128, blockIdx.x*128), row-major ldc. C = alpha * A*B.
// All dims assumed multiples of tile sizes (true for this problem).
// ---------------------------------------------------------------------------
template <bool TRANSB>
__device__ __forceinline__ void gemm_tile(const float* __restrict__ A,
                                          const float* __restrict__ Bm,
                                          float* __restrict__ C,
                                          int K, int lda, int ldb, int ldc,
                                          float alpha) {
    __shared__ float As[8][128];
    __shared__ float Bs[8][128];

    const int tid = threadIdx.x;
    const int row0 = blockIdx.y * 128;
    const int col0 = blockIdx.x * 128;

    // Microtile coordinates: 16x16 thread grid, each does 8 rows x 8 cols.
    const int tr = (tid >> 4) * 8;   // 0..120
    const int tc = (tid & 15) * 8;   // 0..120

    // A slab load mapping: 128 rows x 8 k, one float4 per thread.
    const int a_row = tid >> 1;          // 0..127
    const int a_col = (tid & 1) * 4;     // 0 or 4
    // B slab (no-trans): 8 k x 128 n, one float4 per thread.
    const int b_row = tid >> 5;          // 0..7
    const int b_col = (tid & 31) * 4;    // 0..124
    // B slab (trans): per-n float4 along k.
    const int bt_n  = tid >> 1;          // 0..127
    const int bt_k  = (tid & 1) * 4;     // 0 or 4

    float acc[8][8];
#pragma unroll
    for (int i = 0; i < 8; i++)
#pragma unroll
        for (int j = 0; j < 8; j++) acc[i][j] = 0.0f;

    for (int k0 = 0; k0 < K; k0 += 8) {
        // Load + transpose-store A slab
        float4 av = *reinterpret_cast<const float4*>(
            &A[(size_t)(row0 + a_row) * lda + k0 + a_col]);
        As[a_col + 0][a_row] = av.x;
        As[a_col + 1][a_row] = av.y;
        As[a_col + 2][a_row] = av.z;
        As[a_col + 3][a_row] = av.w;

        if (!TRANSB) {
            float4 bv = *reinterpret_cast<const float4*>(
                &Bm[(size_t)(k0 + b_row) * ldb + col0 + b_col]);
            *reinterpret_cast<float4*>(&Bs[b_row][b_col]) = bv;
        } else {
            float4 bv = *reinterpret_cast<const float4*>(
                &Bm[(size_t)(col0 + bt_n) * ldb + k0 + bt_k]);
            Bs[bt_k + 0][bt_n] = bv.x;
            Bs[bt_k + 1][bt_n] = bv.y;
            Bs[bt_k + 2][bt_n] = bv.z;
            Bs[bt_k + 3][bt_n] = bv.w;
        }
        __syncthreads();

#pragma unroll
        for (int kk = 0; kk < 8; kk++) {
            float a[8], b[8];
            float4 a0 = *reinterpret_cast<const float4*>(&As[kk][tr]);
            float4 a1 = *reinterpret_cast<const float4*>(&As[kk][tr + 4]);
            float4 b0 = *reinterpret_cast<const float4*>(&Bs[kk][tc]);
            float4 b1 = *reinterpret_cast<const float4*>(&Bs[kk][tc + 4]);
            a[0] = a0.x; a[1] = a0.y; a[2] = a0.z; a[3] = a0.w;
            a[4] = a1.x; a[5] = a1.y; a[6] = a1.z; a[7] = a1.w;
            b[0] = b0.x; b[1] = b0.y; b[2] = b0.z; b[3] = b0.w;
            b[4] = b1.x; b[5] = b1.y; b[6] = b1.z; b[7] = b1.w;
#pragma unroll
            for (int i = 0; i < 8; i++)
#pragma unroll
                for (int j = 0; j < 8; j++) acc[i][j] += a[i] * b[j];
        }
        __syncthreads();
    }

    // Epilogue: scaled vectorized store
#pragma unroll
    for (int i = 0; i < 8; i++) {
        float4 v0, v1;
        v0.x = alpha * acc[i][0]; v0.y = alpha * acc[i][1];
        v0.z = alpha * acc[i][2]; v0.w = alpha * acc[i][3];
        v1.x = alpha * acc[i][4]; v1.y = alpha * acc[i][5];
        v1.z = alpha * acc[i][6]; v1.w = alpha * acc[i][7];
        float* cp = &C[(size_t)(row0 + tr + i) * ldc + col0 + tc];
        *reinterpret_cast<float4*>(cp) = v0;
        *reinterpret_cast<float4*>(cp + 4) = v1;
    }
}

// ---------------------------------------------------------------------------
// Kernel 1: fused QKV projections. grid (U/128, M/128, 3)
// ---------------------------------------------------------------------------
__global__ __launch_bounds__(256) void qkv_kernel(const float* __restrict__ x,
                                                  const float* __restrict__ wq,
                                                  const float* __restrict__ wk,
                                                  const float* __restrict__ wv) {
    const float* W;
    float* out;
    if (blockIdx.z == 0)      { W = wq; out = g_q; }
    else if (blockIdx.z == 1) { W = wk; out = g_k; }
    else                      { W = wv; out = g_v; }
    gemm_tile<false>(x, W, out, DD, DD, UU, UU, 1.0f);
}

// ---------------------------------------------------------------------------
// Kernel 2: scores = scale * Q K^T per batch. grid (S/128, S/128, B)
// ---------------------------------------------------------------------------
__global__ __launch_bounds__(256) void scores_kernel(float* __restrict__ attn) {
    const size_t boff = (size_t)blockIdx.z * SS * UU;
    const float scale = 1.0f / sqrtf((float)UU);
    gemm_tile<true>(g_q + boff, g_k + boff,
                    attn + (size_t)blockIdx.z * SS * SS,
                    UU, UU, UU, SS, scale);
}

// ---------------------------------------------------------------------------
// Kernel 3: row softmax in place. grid (B*S), 256 threads, 8 elems/thread.
// ---------------------------------------------------------------------------
__device__ __forceinline__ float warp_max(float v) {
#pragma unroll
    for (int o = 16; o > 0; o >>= 1) v = fmaxf(v, __shfl_xor_sync(0xffffffffu, v, o));
    return v;
}
__device__ __forceinline__ float warp_sum(float v) {
#pragma unroll
    for (int o = 16; o > 0; o >>= 1) v += __shfl_xor_sync(0xffffffffu, v, o);
    return v;
}

__global__ __launch_bounds__(256) void softmax_kernel(float* __restrict__ attn) {
    float* p = attn + (size_t)blockIdx.x * SS;
    const int tid = threadIdx.x;
    __shared__ float red[8];

    float v[8];
#pragma unroll
    for (int j = 0; j < 8; j++) v[j] = p[tid + j * 256];

    // block max
    float m = v[0];
#pragma unroll
    for (int j = 1; j < 8; j++) m = fmaxf(m, v[j]);
    m = warp_max(m);
    if ((tid & 31) == 0) red[tid >> 5] = m;
    __syncthreads();
    if (tid < 32) {
        float t = (tid < 8) ? red[tid] : -INFINITY;
        t = warp_max(t);
        if (tid == 0) red[0] = t;
    }
    __syncthreads();
    m = red[0];

    // exp + block sum
    float s = 0.0f;
#pragma unroll
    for (int j = 0; j < 8; j++) { v[j] = __expf(v[j] - m); s += v[j]; }
    s = warp_sum(s);
    __syncthreads();
    if ((tid & 31) == 0) red[tid >> 5] = s;
    __syncthreads();
    if (tid < 32) {
        float t = (tid < 8) ? red[tid] : 0.0f;
        t = warp_sum(t);
        if (tid == 0) red[0] = t;
    }
    __syncthreads();
    const float inv = 1.0f / red[0];

#pragma unroll
    for (int j = 0; j < 8; j++) p[tid + j * 256] = v[j] * inv;
}

// ---------------------------------------------------------------------------
// Kernel 4: context = attn @ V per batch. grid (U/128, S/128, B)
// ---------------------------------------------------------------------------
__global__ __launch_bounds__(256) void context_kernel(const float* __restrict__ attn,
                                                      float* __restrict__ ctx) {
    const size_t z = blockIdx.z;
    gemm_tile<false>(attn + z * (size_t)SS * SS, g_v + z * (size_t)SS * UU,
                     ctx + z * (size_t)SS * UU,
                     SS, SS, UU, UU, 1.0f);
}

// ---------------------------------------------------------------------------
extern "C" void kernel_launch(void* const* d_in, const int* in_sizes, int n_in,
                              void* d_out, int out_size) {
    const float* x  = (const float*)d_in[0];   // [B,S,D]
    const float* wq = (const float*)d_in[1];   // [D,U]
    const float* wk = (const float*)d_in[2];
    const float* wv = (const float*)d_in[3];

    float* out  = (float*)d_out;
    float* ctx  = out;                                    // [B,S,U]
    float* attn = out + (size_t)BB * SS * UU;             // [B,S,S]

    // 1. QKV projections: [16384x512] x [512x512] x3
    qkv_kernel<<<dim3(UU / 128, (BB * SS) / 128, 3), 256>>>(x, wq, wk, wv);

    // 2. Scores: per batch [2048x512] x [512x2048]^T
    scores_kernel<<<dim3(SS / 128, SS / 128, BB), 256>>>(attn);

    // 3. Softmax rows (in place on attn output)
    softmax_kernel<<<dim3(BB * SS), 256>>>(attn);

    // 4. Context: per batch [2048x2048] x [2048x512]
    context_kernel<<<dim3(UU / 128, SS / 128, BB), 256>>>(attn, ctx);
}

// round 3
// speedup vs baseline: 1.7122x; 1.7122x over previous
#include <cuda_runtime.h>
#include <cuda_bf16.h>
#include <mma.h>
#include <math.h>

using namespace nvcuda;

// Problem constants
#define BB 8
#define SS 2048
#define DD 512
#define UU 512

#define NX ((size_t)BB * SS * DD)      // 8388608
#define NW ((size_t)DD * UU)           // 262144
#define NA ((size_t)BB * SS * SS)      // 33554432

// ---------------------------------------------------------------------------
// Device-global scratch (no allocations allowed)
// ---------------------------------------------------------------------------
__device__ __nv_bfloat16 g_xh[NX], g_xl[NX];
__device__ __nv_bfloat16 g_wqh[NW], g_wql[NW];
__device__ __nv_bfloat16 g_wkh[NW], g_wkl[NW];
__device__ __nv_bfloat16 g_wvh[NW], g_wvl[NW];
__device__ float g_q[NX], g_k[NX], g_v[NX];
__device__ __nv_bfloat16 g_qh[NX], g_ql[NX];
__device__ __nv_bfloat16 g_kh[NX], g_kl[NX];
__device__ __nv_bfloat16 g_vh[NX], g_vl[NX];
__device__ __nv_bfloat16 g_ah[NA], g_al[NA];

// ---------------------------------------------------------------------------
// Split fp32 -> (hi, lo) bf16 pair.  Processes float4 granules.
// ---------------------------------------------------------------------------
__global__ __launch_bounds__(256) void split_kernel(const float* __restrict__ in,
                                                    __nv_bfloat16* __restrict__ hi,
                                                    __nv_bfloat16* __restrict__ lo,
                                                    int n4) {
    int i = blockIdx.x * 256 + threadIdx.x;
    if (i >= n4) return;
    float4 v = reinterpret_cast<const float4*>(in)[i];
    __nv_bfloat16 h0 = __float2bfloat16(v.x);
    __nv_bfloat16 h1 = __float2bfloat16(v.y);
    __nv_bfloat16 h2 = __float2bfloat16(v.z);
    __nv_bfloat16 h3 = __float2bfloat16(v.w);
    __nv_bfloat16 l0 = __float2bfloat16(v.x - __bfloat162float(h0));
    __nv_bfloat16 l1 = __float2bfloat16(v.y - __bfloat162float(h1));
    __nv_bfloat16 l2 = __float2bfloat16(v.z - __bfloat162float(h2));
    __nv_bfloat16 l3 = __float2bfloat16(v.w - __bfloat162float(h3));
    __nv_bfloat162* hp = reinterpret_cast<__nv_bfloat162*>(hi) + i * 2;
    __nv_bfloat162* lp = reinterpret_cast<__nv_bfloat162*>(lo) + i * 2;
    hp[0] = __nv_bfloat162(h0, h1);
    hp[1] = __nv_bfloat162(h2, h3);
    lp[0] = __nv_bfloat162(l0, l1);
    lp[1] = __nv_bfloat162(l2, l3);
}

// ---------------------------------------------------------------------------
// bf16x3 WMMA GEMM tile: 128x128 block tile, BK=32, 8 warps (64x32 per warp).
// C = A*B (fp32 out).  A: MxK row-major (split Ah/Al).
// !TRANSB: B is KxN row-major.  TRANSB: B is NxK row-major (we use B^T).
// All dims multiples of tile sizes.
// ---------------------------------------------------------------------------
template <bool TRANSB>
__device__ __forceinline__ void gemm_bf16x3(const __nv_bfloat16* __restrict__ Ah,
                                            const __nv_bfloat16* __restrict__ Al,
                                            const __nv_bfloat16* __restrict__ Bh,
                                            const __nv_bfloat16* __restrict__ Bl,
                                            float* __restrict__ C,
                                            int K, int lda, int ldb, int ldc) {
    constexpr int APAD = 40;                    // 32 + 8 halves
    constexpr int BROWS = TRANSB ? 128 : 32;
    constexpr int BLD = TRANSB ? 40 : 136;      // padded leading dims

    __shared__ __nv_bfloat16 sAh[128 * APAD], sAl[128 * APAD];
    __shared__ __nv_bfloat16 sBh[BROWS * BLD], sBl[BROWS * BLD];

    const int tid = threadIdx.x;
    const int warp = tid >> 5;
    const int wm = (warp >> 2) * 64;   // warp row offset: 0 / 64
    const int wn = (warp & 3) * 32;    // warp col offset: 0..96
    const int row0 = blockIdx.y * 128;
    const int col0 = blockIdx.x * 128;

    wmma::fragment<wmma::accumulator, 16, 16, 16, float> acc[4][2];
#pragma unroll
    for (int i = 0; i < 4; i++)
#pragma unroll
        for (int j = 0; j < 2; j++) wmma::fill_fragment(acc[i][j], 0.0f);

    for (int k0 = 0; k0 < K; k0 += 32) {
        // ---- stage A tile (128 x 32), int4 = 8 bf16 per load ----
#pragma unroll
        for (int t = 0; t < 2; t++) {
            int idx = tid + t * 256;            // 0..511
            int r = idx >> 2, q = (idx & 3) * 8;
            size_t g = (size_t)(row0 + r) * lda + k0 + q;
            *reinterpret_cast<int4*>(&sAh[r * APAD + q]) =
                *reinterpret_cast<const int4*>(&Ah[g]);
            *reinterpret_cast<int4*>(&sAl[r * APAD + q]) =
                *reinterpret_cast<const int4*>(&Al[g]);
        }
        // ---- stage B tile ----
        if constexpr (TRANSB) {
            // B source rows are n-dim (128), cols are k (32)
#pragma unroll
            for (int t = 0; t < 2; t++) {
                int idx = tid + t * 256;
                int r = idx >> 2, q = (idx & 3) * 8;
                size_t g = (size_t)(col0 + r) * ldb + k0 + q;
                *reinterpret_cast<int4*>(&sBh[r * BLD + q]) =
                    *reinterpret_cast<const int4*>(&Bh[g]);
                *reinterpret_cast<int4*>(&sBl[r * BLD + q]) =
                    *reinterpret_cast<const int4*>(&Bl[g]);
            }
        } else {
            // B source rows are k (32), cols n (128)
#pragma unroll
            for (int t = 0; t < 2; t++) {
                int idx = tid + t * 256;
                int r = idx >> 4, q = (idx & 15) * 8;
                size_t g = (size_t)(k0 + r) * ldb + col0 + q;
                *reinterpret_cast<int4*>(&sBh[r * BLD + q]) =
                    *reinterpret_cast<const int4*>(&Bh[g]);
                *reinterpret_cast<int4*>(&sBl[r * BLD + q]) =
                    *reinterpret_cast<const int4*>(&Bl[g]);
            }
        }
        __syncthreads();

#pragma unroll
        for (int ks = 0; ks < 32; ks += 16) {
            wmma::fragment<wmma::matrix_a, 16, 16, 16, __nv_bfloat16, wmma::row_major> fah[4], fal[4];
#pragma unroll
            for (int i = 0; i < 4; i++) {
                wmma::load_matrix_sync(fah[i], &sAh[(wm + i * 16) * APAD + ks], APAD);
                wmma::load_matrix_sync(fal[i], &sAl[(wm + i * 16) * APAD + ks], APAD);
            }
            if constexpr (TRANSB) {
                wmma::fragment<wmma::matrix_b, 16, 16, 16, __nv_bfloat16, wmma::col_major> fbh[2], fbl[2];
#pragma unroll
                for (int j = 0; j < 2; j++) {
                    wmma::load_matrix_sync(fbh[j], &sBh[(wn + j * 16) * BLD + ks], BLD);
                    wmma::load_matrix_sync(fbl[j], &sBl[(wn + j * 16) * BLD + ks], BLD);
                }
#pragma unroll
                for (int i = 0; i < 4; i++)
#pragma unroll
                    for (int j = 0; j < 2; j++) {
                        wmma::mma_sync(acc[i][j], fah[i], fbh[j], acc[i][j]);
                        wmma::mma_sync(acc[i][j], fah[i], fbl[j], acc[i][j]);
                        wmma::mma_sync(acc[i][j], fal[i], fbh[j], acc[i][j]);
                    }
            } else {
                wmma::fragment<wmma::matrix_b, 16, 16, 16, __nv_bfloat16, wmma::row_major> fbh[2], fbl[2];
#pragma unroll
                for (int j = 0; j < 2; j++) {
                    wmma::load_matrix_sync(fbh[j], &sBh[ks * BLD + wn + j * 16], BLD);
                    wmma::load_matrix_sync(fbl[j], &sBl[ks * BLD + wn + j * 16], BLD);
                }
#pragma unroll
                for (int i = 0; i < 4; i++)
#pragma unroll
                    for (int j = 0; j < 2; j++) {
                        wmma::mma_sync(acc[i][j], fah[i], fbh[j], acc[i][j]);
                        wmma::mma_sync(acc[i][j], fah[i], fbl[j], acc[i][j]);
                        wmma::mma_sync(acc[i][j], fal[i], fbh[j], acc[i][j]);
                    }
            }
        }
        __syncthreads();
    }

    // ---- epilogue: fp32 store ----
#pragma unroll
    for (int i = 0; i < 4; i++)
#pragma unroll
        for (int j = 0; j < 2; j++) {
            wmma::store_matrix_sync(
                &C[(size_t)(row0 + wm + i * 16) * ldc + col0 + wn + j * 16],
                acc[i][j], ldc, wmma::mem_row_major);
        }
}

// ---------------------------------------------------------------------------
// Kernel 1: QKV projections. grid (U/128, M/128, 3)
// ---------------------------------------------------------------------------
__global__ __launch_bounds__(256) void qkv3_kernel() {
    const __nv_bfloat16 *wh, *wl;
    float* out;
    if (blockIdx.z == 0)      { wh = g_wqh; wl = g_wql; out = g_q; }
    else if (blockIdx.z == 1) { wh = g_wkh; wl = g_wkl; out = g_k; }
    else                      { wh = g_wvh; wl = g_wvl; out = g_v; }
    gemm_bf16x3<false>(g_xh, g_xl, wh, wl, out, DD, DD, UU, UU);
}

// ---------------------------------------------------------------------------
// Kernel 2: scores = Q K^T (unscaled; scale folded into softmax).
// grid (S/128, S/128, B)
// ---------------------------------------------------------------------------
__global__ __launch_bounds__(256) void scores3_kernel(float* __restrict__ attn) {
    const size_t boff = (size_t)blockIdx.z * SS * UU;
    gemm_bf16x3<true>(g_qh + boff, g_ql + boff, g_kh + boff, g_kl + boff,
                      attn + (size_t)blockIdx.z * SS * SS, UU, UU, UU, SS);
}

// ---------------------------------------------------------------------------
// Kernel 3: row softmax of (scale * scores) in place + fused bf16 hi/lo split.
// grid (B*S), 256 threads, 8 elems/thread.
// ---------------------------------------------------------------------------
__device__ __forceinline__ float warp_max(float v) {
#pragma unroll
    for (int o = 16; o > 0; o >>= 1) v = fmaxf(v, __shfl_xor_sync(0xffffffffu, v, o));
    return v;
}
__device__ __forceinline__ float warp_sum(float v) {
#pragma unroll
    for (int o = 16; o > 0; o >>= 1) v += __shfl_xor_sync(0xffffffffu, v, o);
    return v;
}

__global__ __launch_bounds__(256) void softmax_split_kernel(float* __restrict__ attn) {
    const size_t rowbase = (size_t)blockIdx.x * SS;
    float* p = attn + rowbase;
    const int tid = threadIdx.x;
    const float scale = 1.0f / sqrtf((float)UU);
    __shared__ float red[8];

    float v[8];
#pragma unroll
    for (int j = 0; j < 8; j++) v[j] = p[tid + j * 256] * scale;

    float m = v[0];
#pragma unroll
    for (int j = 1; j < 8; j++) m = fmaxf(m, v[j]);
    m = warp_max(m);
    if ((tid & 31) == 0) red[tid >> 5] = m;
    __syncthreads();
    if (tid < 32) {
        float t = (tid < 8) ? red[tid] : -INFINITY;
        t = warp_max(t);
        if (tid == 0) red[0] = t;
    }
    __syncthreads();
    m = red[0];

    float s = 0.0f;
#pragma unroll
    for (int j = 0; j < 8; j++) { v[j] = __expf(v[j] - m); s += v[j]; }
    s = warp_sum(s);
    __syncthreads();
    if ((tid & 31) == 0) red[tid >> 5] = s;
    __syncthreads();
    if (tid < 32) {
        float t = (tid < 8) ? red[tid] : 0.0f;
        t = warp_sum(t);
        if (tid == 0) red[0] = t;
    }
    __syncthreads();
    const float inv = 1.0f / red[0];

#pragma unroll
    for (int j = 0; j < 8; j++) {
        float r = v[j] * inv;
        int col = tid + j * 256;
        p[col] = r;
        __nv_bfloat16 h = __float2bfloat16(r);
        g_ah[rowbase + col] = h;
        g_al[rowbase + col] = __float2bfloat16(r - __bfloat162float(h));
    }
}

// ---------------------------------------------------------------------------
// Kernel 4: context = attn @ V per batch. grid (U/128, S/128, B)
// ---------------------------------------------------------------------------
__global__ __launch_bounds__(256) void context3_kernel(float* __restrict__ ctx) {
    const size_t z = blockIdx.z;
    gemm_bf16x3<false>(g_ah + z * (size_t)SS * SS, g_al + z * (size_t)SS * SS,
                       g_vh + z * (size_t)SS * UU, g_vl + z * (size_t)SS * UU,
                       ctx + z * (size_t)SS * UU, SS, SS, UU, UU);
}

// ---------------------------------------------------------------------------
extern "C" void kernel_launch(void* const* d_in, const int* in_sizes, int n_in,
                              void* d_out, int out_size) {
    const float* x  = (const float*)d_in[0];   // [B,S,D]
    const float* wq = (const float*)d_in[1];   // [D,U]
    const float* wk = (const float*)d_in[2];
    const float* wv = (const float*)d_in[3];

    float* out  = (float*)d_out;
    float* ctx  = out;                         // [B,S,U]
    float* attn = out + NX;                    // [B,S,S]

    // Resolve device-global addresses for split targets
    __nv_bfloat16 *xh, *xl, *wqh, *wql, *wkh, *wkl, *wvh, *wvl;
    __nv_bfloat16 *qh, *ql, *kh, *kl, *vh, *vl;
    float *qf, *kf, *vf;
    cudaGetSymbolAddress((void**)&xh,  g_xh);  cudaGetSymbolAddress((void**)&xl,  g_xl);
    cudaGetSymbolAddress((void**)&wqh, g_wqh); cudaGetSymbolAddress((void**)&wql, g_wql);
    cudaGetSymbolAddress((void**)&wkh, g_wkh); cudaGetSymbolAddress((void**)&wkl, g_wkl);
    cudaGetSymbolAddress((void**)&wvh, g_wvh); cudaGetSymbolAddress((void**)&wvl, g_wvl);
    cudaGetSymbolAddress((void**)&qf,  g_q);   cudaGetSymbolAddress((void**)&kf,  g_k);
    cudaGetSymbolAddress((void**)&vf,  g_v);
    cudaGetSymbolAddress((void**)&qh,  g_qh);  cudaGetSymbolAddress((void**)&ql,  g_ql);
    cudaGetSymbolAddress((void**)&kh,  g_kh);  cudaGetSymbolAddress((void**)&kl,  g_kl);
    cudaGetSymbolAddress((void**)&vh,  g_vh);  cudaGetSymbolAddress((void**)&vl,  g_vl);

    const int n4x = (int)(NX / 4);   // 2097152
    const int n4w = (int)(NW / 4);   // 65536

    // 1. split inputs + weights to bf16 hi/lo
    split_kernel<<<(n4x + 255) / 256, 256>>>(x, xh, xl, n4x);
    split_kernel<<<(n4w + 255) / 256, 256>>>(wq, wqh, wql, n4w);
    split_kernel<<<(n4w + 255) / 256, 256>>>(wk, wkh, wkl, n4w);
    split_kernel<<<(n4w + 255) / 256, 256>>>(wv, wvh, wvl, n4w);

    // 2. QKV projections (tensor core, bf16x3)
    qkv3_kernel<<<dim3(UU / 128, (BB * SS) / 128, 3), 256>>>();

    // 3. split Q/K/V
    split_kernel<<<(n4x + 255) / 256, 256>>>(qf, qh, ql, n4x);
    split_kernel<<<(n4x + 255) / 256, 256>>>(kf, kh, kl, n4x);
    split_kernel<<<(n4x + 255) / 256, 256>>>(vf, vh, vl, n4x);

    // 4. scores = Q K^T
    scores3_kernel<<<dim3(SS / 128, SS / 128, BB), 256>>>(attn);

    // 5. softmax (+ scale) + split attn to bf16 hi/lo
    softmax_split_kernel<<<dim3(BB * SS), 256>>>(attn);

    // 6. context = attn @ V
    context3_kernel<<<dim3(UU / 128, SS / 128, BB), 256>>>(ctx);
}

// round 5
// speedup vs baseline: 2.2357x; 1.3057x over previous
#include <cuda_runtime.h>
#include <cuda_bf16.h>
#include <mma.h>
#include <cstdint>
#include <math.h>

using namespace nvcuda;

// Problem constants
#define BB 8
#define SS 2048
#define DD 512
#define UU 512

#define NX ((size_t)BB * SS * DD)      // 8388608
#define NW ((size_t)DD * UU)           // 262144
#define NA ((size_t)BB * SS * SS)     // 33554432

#define SCALE 0.04419417382415922f    // 1/sqrt(512)

// ---------------------------------------------------------------------------
// Device-global scratch (no allocations allowed)
// ---------------------------------------------------------------------------
__device__ __align__(128) __nv_bfloat16 g_xh[NX],  g_xl[NX];     // x splits [B*S][D]
__device__ __align__(128) __nv_bfloat16 g_wqh[NW], g_wql[NW];    // Wq splits [D][U]
__device__ __align__(128) __nv_bfloat16 g_wkh[NW], g_wkl[NW];    // Wk splits [D][U]
__device__ __align__(128) __nv_bfloat16 g_wvth[NW], g_wvtl[NW];  // Wv^T splits [U][D]
__device__ __align__(128) __nv_bfloat16 g_mth[NW], g_mtl[NW];    // Mt = scale*Wk Wq^T [D][D]
__device__ __align__(128) __nv_bfloat16 g_ph[NX],  g_pl[NX];     // P = x Mt^T [B*S][D]
__device__ __align__(128) __nv_bfloat16 g_vth[NX], g_vtl[NX];    // V^T splits [B][U][S]
__device__ __align__(128) __nv_bfloat16 g_ah[NA],  g_al[NA];     // attn splits [B][S][S]

// ---------------------------------------------------------------------------
// Helpers
// ---------------------------------------------------------------------------
__device__ __forceinline__ uint32_t smem_u32(const void* p) {
    uint32_t a;
    asm("{ .reg .u64 t; cvta.to.shared.u64 t, %1; cvt.u32.u64 %0, t; }" : "=r"(a) : "l"(p));
    return a;
}
__device__ __forceinline__ uint32_t pack_bf2(__nv_bfloat16 a, __nv_bfloat16 b) {
    return (uint32_t)__bfloat16_as_ushort(a) | ((uint32_t)__bfloat16_as_ushort(b) << 16);
}

// ---------------------------------------------------------------------------
// bf16x3 mma GEMM: 128x128 CTA tile, BK=32, 256 threads (8 warps, 2x4 grid,
// 64x32 warp tile), cp.async double buffered.  ALL operands K-major:
//   A: MxK row-major (hi/lo), B: NxK row-major (hi/lo).  C = A * B^T.
// MODE 0: fp32 store to Cf.   MODE 1: alpha-scaled bf16 hi/lo split store.
// MODE 2: bf16 hi/lo split TRANSPOSED store (per-batch V^T layout, ldo = SS).
// ---------------------------------------------------------------------------
#define ARR_H 5120                      // 128 * 40 halves per array
#define STG_H 20480                     // 4 arrays per stage
#define SMEM_DYN (2 * STG_H * 2)        // bytes = 81920

__device__ __forceinline__ void stage_arr(uint32_t sdst, const __nv_bfloat16* __restrict__ src,
                                          int r0, int k0, int ld, int tid) {
#pragma unroll
    for (int j = 0; j < 2; j++) {
        int idx = tid + j * 256;                  // 512 chunks of 16B
        int r = idx >> 2, c = idx & 3;
        uint32_t dst = sdst + (uint32_t)(r * 80 + c * 16);
        const void* gp = (const void*)(src + (size_t)(r0 + r) * ld + k0 + c * 8);
        asm volatile("cp.async.cg.shared.global [%0], [%1], 16;" :: "r"(dst), "l"(gp));
    }
}

template <int MODE>
__device__ __forceinline__ void gemm_mma(const __nv_bfloat16* __restrict__ Ah,
                                         const __nv_bfloat16* __restrict__ Al,
                                         const __nv_bfloat16* __restrict__ Bh,
                                         const __nv_bfloat16* __restrict__ Bl,
                                         int K, int lda, int ldb, float alpha,
                                         float* __restrict__ Cf, int ldc,
                                         __nv_bfloat16* __restrict__ Oh,
                                         __nv_bfloat16* __restrict__ Ol, int ldo) {
    extern __shared__ __nv_bfloat16 smem[];

    const int tid  = threadIdx.x;
    const int warp = tid >> 5;
    const int lane = tid & 31;
    const int wm = (warp >> 2) * 64;     // warp row: 0 / 64
    const int wn = (warp & 3) * 32;      // warp col: 0..96
    const int row0 = blockIdx.y * 128;
    const int col0 = blockIdx.x * 128;

    const uint32_t sbase = smem_u32(smem);

    wmma::fragment<wmma::accumulator, 16, 16, 16, float> acc[4][2];
#pragma unroll
    for (int i = 0; i < 4; i++)
#pragma unroll
        for (int j = 0; j < 2; j++) wmma::fill_fragment(acc[i][j], 0.0f);

    const int niter = K >> 5;

    // prologue: stage iter 0 -> buf 0
    {
        uint32_t b0 = sbase;
        stage_arr(b0 + 0 * ARR_H * 2, Ah, row0, 0, lda, tid);
        stage_arr(b0 + 1 * ARR_H * 2, Al, row0, 0, lda, tid);
        stage_arr(b0 + 2 * ARR_H * 2, Bh, col0, 0, ldb, tid);
        stage_arr(b0 + 3 * ARR_H * 2, Bl, col0, 0, ldb, tid);
        asm volatile("cp.async.commit_group;" ::: "memory");
    }

    for (int it = 0; it < niter; it++) {
        const int buf = it & 1;
        if (it + 1 < niter) {
            uint32_t nb = sbase + (uint32_t)((buf ^ 1) * STG_H * 2);
            int k0 = (it + 1) << 5;
            stage_arr(nb + 0 * ARR_H * 2, Ah, row0, k0, lda, tid);
            stage_arr(nb + 1 * ARR_H * 2, Al, row0, k0, lda, tid);
            stage_arr(nb + 2 * ARR_H * 2, Bh, col0, k0, ldb, tid);
            stage_arr(nb + 3 * ARR_H * 2, Bl, col0, k0, ldb, tid);
            asm volatile("cp.async.commit_group;" ::: "memory");
            asm volatile("cp.async.wait_group 1;" ::: "memory");
        } else {
            asm volatile("cp.async.wait_group 0;" ::: "memory");
        }
        __syncthreads();

        const __nv_bfloat16* sAh = smem + buf * STG_H + 0 * ARR_H;
        const __nv_bfloat16* sAl = smem + buf * STG_H + 1 * ARR_H;
        const __nv_bfloat16* sBh = smem + buf * STG_H + 2 * ARR_H;
        const __nv_bfloat16* sBl = smem + buf * STG_H + 3 * ARR_H;

#pragma unroll
        for (int ks = 0; ks < 32; ks += 16) {
            wmma::fragment<wmma::matrix_b, 16, 16, 16, __nv_bfloat16, wmma::col_major> fbh[2], fbl[2];
#pragma unroll
            for (int j = 0; j < 2; j++) {
                wmma::load_matrix_sync(fbh[j], &sBh[(wn + j * 16) * 40 + ks], 40);
                wmma::load_matrix_sync(fbl[j], &sBl[(wn + j * 16) * 40 + ks], 40);
            }
#pragma unroll
            for (int i = 0; i < 4; i++) {
                wmma::fragment<wmma::matrix_a, 16, 16, 16, __nv_bfloat16, wmma::row_major> fah, fal;
                wmma::load_matrix_sync(fah, &sAh[(wm + i * 16) * 40 + ks], 40);
                wmma::load_matrix_sync(fal, &sAl[(wm + i * 16) * 40 + ks], 40);
#pragma unroll
                for (int j = 0; j < 2; j++) {
                    wmma::mma_sync(acc[i][j], fah, fbh[j], acc[i][j]);
                    wmma::mma_sync(acc[i][j], fah, fbl[j], acc[i][j]);
                    wmma::mma_sync(acc[i][j], fal, fbh[j], acc[i][j]);
                }
            }
        }
        __syncthreads();
    }

    // ------------------------- epilogue -------------------------
    if constexpr (MODE == 0) {
#pragma unroll
        for (int i = 0; i < 4; i++)
#pragma unroll
            for (int j = 0; j < 2; j++)
                wmma::store_matrix_sync(
                    &Cf[(size_t)(row0 + wm + i * 16) * ldc + col0 + wn + j * 16],
                    acc[i][j], ldc, wmma::mem_row_major);
    } else {
        __shared__ float eps[8][16 * 24];
        float* ew = eps[warp];
        if constexpr (MODE == 1) {
#pragma unroll
            for (int i = 0; i < 4; i++)
#pragma unroll
                for (int j = 0; j < 2; j++) {
                    wmma::store_matrix_sync(ew, acc[i][j], 24, wmma::mem_row_major);
                    __syncwarp();
                    int r = lane >> 1, cb = (lane & 1) * 8;
                    float v[8];
#pragma unroll
                    for (int e = 0; e < 8; e++) v[e] = ew[r * 24 + cb + e] * alpha;
                    uint4 hp, lp;
                    __nv_bfloat16 h[8];
#pragma unroll
                    for (int e = 0; e < 8; e++) h[e] = __float2bfloat16(v[e]);
                    hp.x = pack_bf2(h[0], h[1]); hp.y = pack_bf2(h[2], h[3]);
                    hp.z = pack_bf2(h[4], h[5]); hp.w = pack_bf2(h[6], h[7]);
                    __nv_bfloat16 l[8];
#pragma unroll
                    for (int e = 0; e < 8; e++) l[e] = __float2bfloat16(v[e] - __bfloat162float(h[e]));
                    lp.x = pack_bf2(l[0], l[1]); lp.y = pack_bf2(l[2], l[3]);
                    lp.z = pack_bf2(l[4], l[5]); lp.w = pack_bf2(l[6], l[7]);
                    size_t idx = (size_t)(row0 + wm + i * 16 + r) * ldo + col0 + wn + j * 16 + cb;
                    *reinterpret_cast<uint4*>(&Oh[idx]) = hp;
                    *reinterpret_cast<uint4*>(&Ol[idx]) = lp;
                    __syncwarp();
                }
        } else {
            // MODE 2: transposed split (V^T), row0 indexes tokens [B*S]
            const int b  = row0 >> 11;               // SS == 2048
            const int s0 = (row0 & 2047) + wm;
            __nv_bfloat16* ohb = Oh + (size_t)b * UU * SS;
            __nv_bfloat16* olb = Ol + (size_t)b * UU * SS;
#pragma unroll
            for (int i = 0; i < 4; i++)
#pragma unroll
                for (int j = 0; j < 2; j++) {
                    wmma::store_matrix_sync(ew, acc[i][j], 24, wmma::mem_row_major);
                    __syncwarp();
                    if (lane < 16) {
                        int u = lane;
                        float v[16];
#pragma unroll
                        for (int r = 0; r < 16; r++) v[r] = ew[r * 24 + u];
                        uint32_t hw[8], lw[8];
#pragma unroll
                        for (int e = 0; e < 8; e++) {
                            __nv_bfloat16 ha = __float2bfloat16(v[2 * e]);
                            __nv_bfloat16 hb = __float2bfloat16(v[2 * e + 1]);
                            hw[e] = pack_bf2(ha, hb);
                            lw[e] = pack_bf2(__float2bfloat16(v[2 * e] - __bfloat162float(ha)),
                                             __float2bfloat16(v[2 * e + 1] - __bfloat162float(hb)));
                        }
                        size_t idx = (size_t)(col0 + wn + j * 16 + u) * SS + s0 + i * 16;
                        uint4 h0, h1, l0, l1;
                        h0.x = hw[0]; h0.y = hw[1]; h0.z = hw[2]; h0.w = hw[3];
                        h1.x = hw[4]; h1.y = hw[5]; h1.z = hw[6]; h1.w = hw[7];
                        l0.x = lw[0]; l0.y = lw[1]; l0.z = lw[2]; l0.w = lw[3];
                        l1.x = lw[4]; l1.y = lw[5]; l1.z = lw[6]; l1.w = lw[7];
                        *reinterpret_cast<uint4*>(&ohb[idx])     = h0;
                        *reinterpret_cast<uint4*>(&ohb[idx + 8]) = h1;
                        *reinterpret_cast<uint4*>(&olb[idx])     = l0;
                        *reinterpret_cast<uint4*>(&olb[idx + 8]) = l1;
                    }
                    __syncwarp();
                }
        }
    }
}

// ---------------------------------------------------------------------------
// GEMM kernel wrappers
// ---------------------------------------------------------------------------
__global__ __launch_bounds__(256) void mt_kernel() {
    // Mt[d2][d1] = scale * sum_u Wk[d2][u] * Wq[d1][u]
    gemm_mma<1>(g_wkh, g_wkl, g_wqh, g_wql, UU, UU, UU, SCALE,
                nullptr, 0, g_mth, g_mtl, DD);
}

__global__ __launch_bounds__(256) void p_kernel() {
    // P = x @ Mt^T  -> [B*S][D] split
    gemm_mma<1>(g_xh, g_xl, g_mth, g_mtl, DD, DD, DD, 1.0f,
                nullptr, 0, g_ph, g_pl, DD);
}

__global__ __launch_bounds__(256) void v_kernel() {
    // V = x @ Wv, stored transposed per batch as V^T [B][U][S] split
    gemm_mma<2>(g_xh, g_xl, g_wvth, g_wvtl, DD, DD, DD, 1.0f,
                nullptr, 0, g_vth, g_vtl, SS);
}

__global__ __launch_bounds__(256) void scores_kernel(float* __restrict__ attn) {
    const size_t zo = (size_t)blockIdx.z * SS * DD;
    gemm_mma<0>(g_ph + zo, g_pl + zo, g_xh + zo, g_xl + zo, DD, DD, DD, 1.0f,
                attn + (size_t)blockIdx.z * SS * SS, SS, nullptr, nullptr, 0);
}

__global__ __launch_bounds__(256) void context_kernel(float* __restrict__ ctx) {
    const size_t z = blockIdx.z;
    gemm_mma<0>(g_ah + z * (size_t)SS * SS, g_al + z * (size_t)SS * SS,
                g_vth + z * (size_t)UU * SS, g_vtl + z * (size_t)UU * SS,
                SS, SS, SS, 1.0f,
                ctx + z * (size_t)SS * UU, UU, nullptr, nullptr, 0);
}

// ---------------------------------------------------------------------------
// Elementwise kernels
// ---------------------------------------------------------------------------
__global__ __launch_bounds__(256) void split_x_kernel(const float* __restrict__ in) {
    int i = blockIdx.x * 256 + threadIdx.x;     // float4 granules, NX/4 total
    float4 v = reinterpret_cast<const float4*>(in)[i];
    __nv_bfloat16 h0 = __float2bfloat16(v.x), h1 = __float2bfloat16(v.y);
    __nv_bfloat16 h2 = __float2bfloat16(v.z), h3 = __float2bfloat16(v.w);
    uint2 hp, lp;
    hp.x = pack_bf2(h0, h1); hp.y = pack_bf2(h2, h3);
    lp.x = pack_bf2(__float2bfloat16(v.x - __bfloat162float(h0)),
                    __float2bfloat16(v.y - __bfloat162float(h1)));
    lp.y = pack_bf2(__float2bfloat16(v.z - __bfloat162float(h2)),
                    __float2bfloat16(v.w - __bfloat162float(h3)));
    reinterpret_cast<uint2*>(g_xh)[i] = hp;
    reinterpret_cast<uint2*>(g_xl)[i] = lp;
}

__global__ __launch_bounds__(256) void splitW_kernel(const float* __restrict__ wq,
                                                     const float* __restrict__ wk) {
    const float* src = (blockIdx.y == 0) ? wq : wk;
    __nv_bfloat16* oh = (blockIdx.y == 0) ? g_wqh : g_wkh;
    __nv_bfloat16* ol = (blockIdx.y == 0) ? g_wql : g_wkl;
    int i = blockIdx.x * 256 + threadIdx.x;     // NW/4 granules
    float4 v = reinterpret_cast<const float4*>(src)[i];
    __nv_bfloat16 h0 = __float2bfloat16(v.x), h1 = __float2bfloat16(v.y);
    __nv_bfloat16 h2 = __float2bfloat16(v.z), h3 = __float2bfloat16(v.w);
    uint2 hp, lp;
    hp.x = pack_bf2(h0, h1); hp.y = pack_bf2(h2, h3);
    lp.x = pack_bf2(__float2bfloat16(v.x - __bfloat162float(h0)),
                    __float2bfloat16(v.y - __bfloat162float(h1)));
    lp.y = pack_bf2(__float2bfloat16(v.z - __bfloat162float(h2)),
                    __float2bfloat16(v.w - __bfloat162float(h3)));
    reinterpret_cast<uint2*>(oh)[i] = hp;
    reinterpret_cast<uint2*>(ol)[i] = lp;
}

__global__ void wsplitT_kernel(const float* __restrict__ wv) {
    __shared__ float t[32][33];
    const int u0 = blockIdx.x * 32, d0 = blockIdx.y * 32;
    const int tx = threadIdx.x, ty = threadIdx.y;
#pragma unroll
    for (int p = 0; p < 4; p++)
        t[ty + p * 8][tx] = wv[(size_t)(d0 + ty + p * 8) * UU + u0 + tx];
    __syncthreads();
#pragma unroll
    for (int p = 0; p < 4; p++) {
        float v = t[tx][ty + p * 8];
        __nv_bfloat16 h = __float2bfloat16(v);
        size_t idx = (size_t)(u0 + ty + p * 8) * DD + d0 + tx;
        g_wvth[idx] = h;
        g_wvtl[idx] = __float2bfloat16(v - __bfloat162float(h));
    }
}

__device__ __forceinline__ float warp_max(float v) {
#pragma unroll
    for (int o = 16; o > 0; o >>= 1) v = fmaxf(v, __shfl_xor_sync(0xffffffffu, v, o));
    return v;
}
__device__ __forceinline__ float warp_sum(float v) {
#pragma unroll
    for (int o = 16; o > 0; o >>= 1) v += __shfl_xor_sync(0xffffffffu, v, o);
    return v;
}

__global__ __launch_bounds__(256) void softmax_split_kernel(float* __restrict__ attn) {
    const size_t rowbase = (size_t)blockIdx.x * SS;
    float* p = attn + rowbase;
    const int tid = threadIdx.x;
    __shared__ float red[8];

    float v[8];
#pragma unroll
    for (int j = 0; j < 8; j++) v[j] = p[tid + j * 256];

    float m = v[0];
#pragma unroll
    for (int j = 1; j < 8; j++) m = fmaxf(m, v[j]);
    m = warp_max(m);
    if ((tid & 31) == 0) red[tid >> 5] = m;
    __syncthreads();
    if (tid < 32) {
        float t = (tid < 8) ? red[tid] : -INFINITY;
        t = warp_max(t);
        if (tid == 0) red[0] = t;
    }
    __syncthreads();
    m = red[0];

    float s = 0.0f;
#pragma unroll
    for (int j = 0; j < 8; j++) { v[j] = __expf(v[j] - m); s += v[j]; }
    s = warp_sum(s);
    __syncthreads();
    if ((tid & 31) == 0) red[tid >> 5] = s;
    __syncthreads();
    if (tid < 32) {
        float t = (tid < 8) ? red[tid] : 0.0f;
        t = warp_sum(t);
        if (tid == 0) red[0] = t;
    }
    __syncthreads();
    const float inv = 1.0f / red[0];

#pragma unroll
    for (int j = 0; j < 8; j++) {
        float r = v[j] * inv;
        int col = tid + j * 256;
        p[col] = r;
        __nv_bfloat16 h = __float2bfloat16(r);
        g_ah[rowbase + col] = h;
        g_al[rowbase + col] = __float2bfloat16(r - __bfloat162float(h));
    }
}

// ---------------------------------------------------------------------------
extern "C" void kernel_launch(void* const* d_in, const int* in_sizes, int n_in,
                              void* d_out, int out_size) {
    const float* x  = (const float*)d_in[0];   // [B,S,D]
    const float* wq = (const float*)d_in[1];   // [D,U]
    const float* wk = (const float*)d_in[2];
    const float* wv = (const float*)d_in[3];

    float* out  = (float*)d_out;
    float* ctx  = out;                         // [B,S,U]
    float* attn = out + NX;                    // [B,S,S]

    cudaFuncSetAttribute(mt_kernel,      cudaFuncAttributeMaxDynamicSharedMemorySize, SMEM_DYN);
    cudaFuncSetAttribute(p_kernel,       cudaFuncAttributeMaxDynamicSharedMemorySize, SMEM_DYN);
    cudaFuncSetAttribute(v_kernel,       cudaFuncAttributeMaxDynamicSharedMemorySize, SMEM_DYN);
    cudaFuncSetAttribute(scores_kernel,  cudaFuncAttributeMaxDynamicSharedMemorySize, SMEM_DYN);
    cudaFuncSetAttribute(context_kernel, cudaFuncAttributeMaxDynamicSharedMemorySize, SMEM_DYN);

    // 1. splits: x, Wq, Wk (plain), Wv (transposed)
    split_x_kernel<<<(int)(NX / 4 / 256), 256>>>(x);
    splitW_kernel<<<dim3((int)(NW / 4 / 256), 2), 256>>>(wq, wk);
    wsplitT_kernel<<<dim3(UU / 32, DD / 32), dim3(32, 8)>>>(wv);

    // 2. Mt = scale * Wk @ Wq^T  [512x512]
    mt_kernel<<<dim3(4, 4), 256, SMEM_DYN>>>();

    // 3. P = x @ Mt^T  [16384x512], V^T = (x @ Wv)^T  [B][512][2048]
    p_kernel<<<dim3(4, 128), 256, SMEM_DYN>>>();
    v_kernel<<<dim3(4, 128), 256, SMEM_DYN>>>();

    // 4. scores = P @ x^T per batch (scale already folded into Mt)
    scores_kernel<<<dim3(16, 16, BB), 256, SMEM_DYN>>>(attn);

    // 5. softmax + bf16 hi/lo split of attn
    softmax_split_kernel<<<dim3(BB * SS), 256>>>(attn);

    // 6. context = attn @ V per batch
    context_kernel<<<dim3(4, 16, BB), 256, SMEM_DYN>>>(ctx);
}

// round 6
// speedup vs baseline: 2.2380x; 1.0010x over previous
#include <cuda_runtime.h>
#include <cuda_bf16.h>
#include <mma.h>
#include <cstdint>
#include <math.h>

using namespace nvcuda;

// Problem constants
#define BB 8
#define SS 2048
#define DD 512
#define UU 512

#define NX ((size_t)BB * SS * DD)      // 8388608
#define NW ((size_t)DD * UU)           // 262144
#define NA ((size_t)BB * SS * SS)     // 33554432

#define SCALE 0.04419417382415922f    // 1/sqrt(512)

// ---------------------------------------------------------------------------
// Device-global scratch (no allocations allowed)
// ---------------------------------------------------------------------------
__device__ __align__(128) __nv_bfloat16 g_xh[NX],  g_xl[NX];     // x splits [B*S][D]
__device__ __align__(128) __nv_bfloat16 g_wqh[NW], g_wql[NW];    // Wq splits [D][U]
__device__ __align__(128) __nv_bfloat16 g_wkh[NW], g_wkl[NW];    // Wk splits [D][U]
__device__ __align__(128) __nv_bfloat16 g_wvth[NW], g_wvtl[NW];  // Wv^T splits [U][D]
__device__ __align__(128) __nv_bfloat16 g_mth[NW], g_mtl[NW];    // Mt = scale*Wk Wq^T [D][D]
__device__ __align__(128) __nv_bfloat16 g_ph[NX],  g_pl[NX];     // P = x Mt^T [B*S][D]
__device__ __align__(128) __nv_bfloat16 g_vth[NX], g_vtl[NX];    // V^T splits [B][U][S]
__device__ __align__(128) __nv_bfloat16 g_ah[NA],  g_al[NA];     // attn splits [B][S][S]

// ---------------------------------------------------------------------------
// Helpers
// ---------------------------------------------------------------------------
__device__ __forceinline__ uint32_t smem_u32(const void* p) {
    uint32_t a;
    asm("{ .reg .u64 t; cvta.to.shared.u64 t, %1; cvt.u32.u64 %0, t; }" : "=r"(a) : "l"(p));
    return a;
}
__device__ __forceinline__ uint32_t pack_bf2(__nv_bfloat16 a, __nv_bfloat16 b) {
    return (uint32_t)__bfloat16_as_ushort(a) | ((uint32_t)__bfloat16_as_ushort(b) << 16);
}

// ---------------------------------------------------------------------------
// bf16x3 mma GEMM: 128x128 CTA tile, BK=32, 256 threads (8 warps, 2x4 grid,
// 64x32 warp tile), cp.async double buffered.  ALL operands K-major:
//   A: MxK row-major (hi/lo), B: NxK row-major (hi/lo).  C = A * B^T.
// MODE 0: fp32 store to Cf.   MODE 1: alpha-scaled bf16 hi/lo split store.
// MODE 2: bf16 hi/lo split TRANSPOSED store (per-batch V^T layout, ldo = SS).
// ---------------------------------------------------------------------------
#define ARR_H 5120                      // 128 * 40 halves per array
#define STG_H 20480                     // 4 arrays per stage
#define SMEM_DYN (2 * STG_H * 2)        // bytes = 81920

__device__ __forceinline__ void stage_arr(uint32_t sdst, const __nv_bfloat16* __restrict__ src,
                                          int r0, int k0, int ld, int tid) {
#pragma unroll
    for (int j = 0; j < 2; j++) {
        int idx = tid + j * 256;                  // 512 chunks of 16B
        int r = idx >> 2, c = idx & 3;
        uint32_t dst = sdst + (uint32_t)(r * 80 + c * 16);
        const void* gp = (const void*)(src + (size_t)(r0 + r) * ld + k0 + c * 8);
        asm volatile("cp.async.cg.shared.global [%0], [%1], 16;" :: "r"(dst), "l"(gp));
    }
}

template <int MODE>
__device__ __forceinline__ void gemm_mma(const __nv_bfloat16* __restrict__ Ah,
                                         const __nv_bfloat16* __restrict__ Al,
                                         const __nv_bfloat16* __restrict__ Bh,
                                         const __nv_bfloat16* __restrict__ Bl,
                                         int K, int lda, int ldb, float alpha,
                                         float* __restrict__ Cf, int ldc,
                                         __nv_bfloat16* __restrict__ Oh,
                                         __nv_bfloat16* __restrict__ Ol, int ldo) {
    extern __shared__ __nv_bfloat16 smem[];

    const int tid  = threadIdx.x;
    const int warp = tid >> 5;
    const int lane = tid & 31;
    const int wm = (warp >> 2) * 64;     // warp row: 0 / 64
    const int wn = (warp & 3) * 32;      // warp col: 0..96
    const int row0 = blockIdx.y * 128;
    const int col0 = blockIdx.x * 128;

    const uint32_t sbase = smem_u32(smem);

    wmma::fragment<wmma::accumulator, 16, 16, 16, float> acc[4][2];
#pragma unroll
    for (int i = 0; i < 4; i++)
#pragma unroll
        for (int j = 0; j < 2; j++) wmma::fill_fragment(acc[i][j], 0.0f);

    const int niter = K >> 5;

    // prologue: stage iter 0 -> buf 0
    {
        uint32_t b0 = sbase;
        stage_arr(b0 + 0 * ARR_H * 2, Ah, row0, 0, lda, tid);
        stage_arr(b0 + 1 * ARR_H * 2, Al, row0, 0, lda, tid);
        stage_arr(b0 + 2 * ARR_H * 2, Bh, col0, 0, ldb, tid);
        stage_arr(b0 + 3 * ARR_H * 2, Bl, col0, 0, ldb, tid);
        asm volatile("cp.async.commit_group;" ::: "memory");
    }

    for (int it = 0; it < niter; it++) {
        const int buf = it & 1;
        if (it + 1 < niter) {
            uint32_t nb = sbase + (uint32_t)((buf ^ 1) * STG_H * 2);
            int k0 = (it + 1) << 5;
            stage_arr(nb + 0 * ARR_H * 2, Ah, row0, k0, lda, tid);
            stage_arr(nb + 1 * ARR_H * 2, Al, row0, k0, lda, tid);
            stage_arr(nb + 2 * ARR_H * 2, Bh, col0, k0, ldb, tid);
            stage_arr(nb + 3 * ARR_H * 2, Bl, col0, k0, ldb, tid);
            asm volatile("cp.async.commit_group;" ::: "memory");
            asm volatile("cp.async.wait_group 1;" ::: "memory");
        } else {
            asm volatile("cp.async.wait_group 0;" ::: "memory");
        }
        __syncthreads();

        const __nv_bfloat16* sAh = smem + buf * STG_H + 0 * ARR_H;
        const __nv_bfloat16* sAl = smem + buf * STG_H + 1 * ARR_H;
        const __nv_bfloat16* sBh = smem + buf * STG_H + 2 * ARR_H;
        const __nv_bfloat16* sBl = smem + buf * STG_H + 3 * ARR_H;

#pragma unroll
        for (int ks = 0; ks < 32; ks += 16) {
            wmma::fragment<wmma::matrix_b, 16, 16, 16, __nv_bfloat16, wmma::col_major> fbh[2], fbl[2];
#pragma unroll
            for (int j = 0; j < 2; j++) {
                wmma::load_matrix_sync(fbh[j], &sBh[(wn + j * 16) * 40 + ks], 40);
                wmma::load_matrix_sync(fbl[j], &sBl[(wn + j * 16) * 40 + ks], 40);
            }
#pragma unroll
            for (int i = 0; i < 4; i++) {
                wmma::fragment<wmma::matrix_a, 16, 16, 16, __nv_bfloat16, wmma::row_major> fah, fal;
                wmma::load_matrix_sync(fah, &sAh[(wm + i * 16) * 40 + ks], 40);
                wmma::load_matrix_sync(fal, &sAl[(wm + i * 16) * 40 + ks], 40);
#pragma unroll
                for (int j = 0; j < 2; j++) {
                    wmma::mma_sync(acc[i][j], fah, fbh[j], acc[i][j]);
                    wmma::mma_sync(acc[i][j], fah, fbl[j], acc[i][j]);
                    wmma::mma_sync(acc[i][j], fal, fbh[j], acc[i][j]);
                }
            }
        }
        __syncthreads();
    }

    // ------------------------- epilogue -------------------------
    if constexpr (MODE == 0) {
#pragma unroll
        for (int i = 0; i < 4; i++)
#pragma unroll
            for (int j = 0; j < 2; j++)
                wmma::store_matrix_sync(
                    &Cf[(size_t)(row0 + wm + i * 16) * ldc + col0 + wn + j * 16],
                    acc[i][j], ldc, wmma::mem_row_major);
    } else {
        __shared__ float eps[8][16 * 24];
        float* ew = eps[warp];
        if constexpr (MODE == 1) {
#pragma unroll
            for (int i = 0; i < 4; i++)
#pragma unroll
                for (int j = 0; j < 2; j++) {
                    wmma::store_matrix_sync(ew, acc[i][j], 24, wmma::mem_row_major);
                    __syncwarp();
                    int r = lane >> 1, cb = (lane & 1) * 8;
                    float v[8];
#pragma unroll
                    for (int e = 0; e < 8; e++) v[e] = ew[r * 24 + cb + e] * alpha;
                    uint4 hp, lp;
                    __nv_bfloat16 h[8];
#pragma unroll
                    for (int e = 0; e < 8; e++) h[e] = __float2bfloat16(v[e]);
                    hp.x = pack_bf2(h[0], h[1]); hp.y = pack_bf2(h[2], h[3]);
                    hp.z = pack_bf2(h[4], h[5]); hp.w = pack_bf2(h[6], h[7]);
                    __nv_bfloat16 l[8];
#pragma unroll
                    for (int e = 0; e < 8; e++) l[e] = __float2bfloat16(v[e] - __bfloat162float(h[e]));
                    lp.x = pack_bf2(l[0], l[1]); lp.y = pack_bf2(l[2], l[3]);
                    lp.z = pack_bf2(l[4], l[5]); lp.w = pack_bf2(l[6], l[7]);
                    size_t idx = (size_t)(row0 + wm + i * 16 + r) * ldo + col0 + wn + j * 16 + cb;
                    *reinterpret_cast<uint4*>(&Oh[idx]) = hp;
                    *reinterpret_cast<uint4*>(&Ol[idx]) = lp;
                    __syncwarp();
                }
        } else {
            // MODE 2: transposed split (V^T), row0 indexes tokens [B*S]
            const int b  = row0 >> 11;               // SS == 2048
            const int s0 = (row0 & 2047) + wm;
            __nv_bfloat16* ohb = Oh + (size_t)b * UU * SS;
            __nv_bfloat16* olb = Ol + (size_t)b * UU * SS;
#pragma unroll
            for (int i = 0; i < 4; i++)
#pragma unroll
                for (int j = 0; j < 2; j++) {
                    wmma::store_matrix_sync(ew, acc[i][j], 24, wmma::mem_row_major);
                    __syncwarp();
                    if (lane < 16) {
                        int u = lane;
                        float v[16];
#pragma unroll
                        for (int r = 0; r < 16; r++) v[r] = ew[r * 24 + u];
                        uint32_t hw[8], lw[8];
#pragma unroll
                        for (int e = 0; e < 8; e++) {
                            __nv_bfloat16 ha = __float2bfloat16(v[2 * e]);
                            __nv_bfloat16 hb = __float2bfloat16(v[2 * e + 1]);
                            hw[e] = pack_bf2(ha, hb);
                            lw[e] = pack_bf2(__float2bfloat16(v[2 * e] - __bfloat162float(ha)),
                                             __float2bfloat16(v[2 * e + 1] - __bfloat162float(hb)));
                        }
                        size_t idx = (size_t)(col0 + wn + j * 16 + u) * SS + s0 + i * 16;
                        uint4 h0, h1, l0, l1;
                        h0.x = hw[0]; h0.y = hw[1]; h0.z = hw[2]; h0.w = hw[3];
                        h1.x = hw[4]; h1.y = hw[5]; h1.z = hw[6]; h1.w = hw[7];
                        l0.x = lw[0]; l0.y = lw[1]; l0.z = lw[2]; l0.w = lw[3];
                        l1.x = lw[4]; l1.y = lw[5]; l1.z = lw[6]; l1.w = lw[7];
                        *reinterpret_cast<uint4*>(&ohb[idx])     = h0;
                        *reinterpret_cast<uint4*>(&ohb[idx + 8]) = h1;
                        *reinterpret_cast<uint4*>(&olb[idx])     = l0;
                        *reinterpret_cast<uint4*>(&olb[idx + 8]) = l1;
                    }
                    __syncwarp();
                }
        }
    }
}

// ---------------------------------------------------------------------------
// GEMM kernel wrappers
// ---------------------------------------------------------------------------
__global__ __launch_bounds__(256) void mt_kernel() {
    // Mt[d2][d1] = scale * sum_u Wk[d2][u] * Wq[d1][u]
    gemm_mma<1>(g_wkh, g_wkl, g_wqh, g_wql, UU, UU, UU, SCALE,
                nullptr, 0, g_mth, g_mtl, DD);
}

__global__ __launch_bounds__(256) void p_kernel() {
    // P = x @ Mt^T  -> [B*S][D] split
    gemm_mma<1>(g_xh, g_xl, g_mth, g_mtl, DD, DD, DD, 1.0f,
                nullptr, 0, g_ph, g_pl, DD);
}

__global__ __launch_bounds__(256) void v_kernel() {
    // V = x @ Wv, stored transposed per batch as V^T [B][U][S] split
    gemm_mma<2>(g_xh, g_xl, g_wvth, g_wvtl, DD, DD, DD, 1.0f,
                nullptr, 0, g_vth, g_vtl, SS);
}

__global__ __launch_bounds__(256) void scores_kernel(float* __restrict__ attn) {
    const size_t zo = (size_t)blockIdx.z * SS * DD;
    gemm_mma<0>(g_ph + zo, g_pl + zo, g_xh + zo, g_xl + zo, DD, DD, DD, 1.0f,
                attn + (size_t)blockIdx.z * SS * SS, SS, nullptr, nullptr, 0);
}

__global__ __launch_bounds__(256) void context_kernel(float* __restrict__ ctx) {
    const size_t z = blockIdx.z;
    gemm_mma<0>(g_ah + z * (size_t)SS * SS, g_al + z * (size_t)SS * SS,
                g_vth + z * (size_t)UU * SS, g_vtl + z * (size_t)UU * SS,
                SS, SS, SS, 1.0f,
                ctx + z * (size_t)SS * UU, UU, nullptr, nullptr, 0);
}

// ---------------------------------------------------------------------------
// Elementwise kernels
// ---------------------------------------------------------------------------
__global__ __launch_bounds__(256) void split_x_kernel(const float* __restrict__ in) {
    int i = blockIdx.x * 256 + threadIdx.x;     // float4 granules, NX/4 total
    float4 v = reinterpret_cast<const float4*>(in)[i];
    __nv_bfloat16 h0 = __float2bfloat16(v.x), h1 = __float2bfloat16(v.y);
    __nv_bfloat16 h2 = __float2bfloat16(v.z), h3 = __float2bfloat16(v.w);
    uint2 hp, lp;
    hp.x = pack_bf2(h0, h1); hp.y = pack_bf2(h2, h3);
    lp.x = pack_bf2(__float2bfloat16(v.x - __bfloat162float(h0)),
                    __float2bfloat16(v.y - __bfloat162float(h1)));
    lp.y = pack_bf2(__float2bfloat16(v.z - __bfloat162float(h2)),
                    __float2bfloat16(v.w - __bfloat162float(h3)));
    reinterpret_cast<uint2*>(g_xh)[i] = hp;
    reinterpret_cast<uint2*>(g_xl)[i] = lp;
}

__global__ __launch_bounds__(256) void splitW_kernel(const float* __restrict__ wq,
                                                     const float* __restrict__ wk) {
    const float* src = (blockIdx.y == 0) ? wq : wk;
    __nv_bfloat16* oh = (blockIdx.y == 0) ? g_wqh : g_wkh;
    __nv_bfloat16* ol = (blockIdx.y == 0) ? g_wql : g_wkl;
    int i = blockIdx.x * 256 + threadIdx.x;     // NW/4 granules
    float4 v = reinterpret_cast<const float4*>(src)[i];
    __nv_bfloat16 h0 = __float2bfloat16(v.x), h1 = __float2bfloat16(v.y);
    __nv_bfloat16 h2 = __float2bfloat16(v.z), h3 = __float2bfloat16(v.w);
    uint2 hp, lp;
    hp.x = pack_bf2(h0, h1); hp.y = pack_bf2(h2, h3);
    lp.x = pack_bf2(__float2bfloat16(v.x - __bfloat162float(h0)),
                    __float2bfloat16(v.y - __bfloat162float(h1)));
    lp.y = pack_bf2(__float2bfloat16(v.z - __bfloat162float(h2)),
                    __float2bfloat16(v.w - __bfloat162float(h3)));
    reinterpret_cast<uint2*>(oh)[i] = hp;
    reinterpret_cast<uint2*>(ol)[i] = lp;
}

__global__ void wsplitT_kernel(const float* __restrict__ wv) {
    __shared__ float t[32][33];
    const int u0 = blockIdx.x * 32, d0 = blockIdx.y * 32;
    const int tx = threadIdx.x, ty = threadIdx.y;
#pragma unroll
    for (int p = 0; p < 4; p++)
        t[ty + p * 8][tx] = wv[(size_t)(d0 + ty + p * 8) * UU + u0 + tx];
    __syncthreads();
#pragma unroll
    for (int p = 0; p < 4; p++) {
        float v = t[tx][ty + p * 8];
        __nv_bfloat16 h = __float2bfloat16(v);
        size_t idx = (size_t)(u0 + ty + p * 8) * DD + d0 + tx;
        g_wvth[idx] = h;
        g_wvtl[idx] = __float2bfloat16(v - __bfloat162float(h));
    }
}

__device__ __forceinline__ float warp_max(float v) {
#pragma unroll
    for (int o = 16; o > 0; o >>= 1) v = fmaxf(v, __shfl_xor_sync(0xffffffffu, v, o));
    return v;
}
__device__ __forceinline__ float warp_sum(float v) {
#pragma unroll
    for (int o = 16; o > 0; o >>= 1) v += __shfl_xor_sync(0xffffffffu, v, o);
    return v;
}

__global__ __launch_bounds__(256) void softmax_split_kernel(float* __restrict__ attn) {
    const size_t rowbase = (size_t)blockIdx.x * SS;
    float* p = attn + rowbase;
    const int tid = threadIdx.x;
    __shared__ float red[8];

    float v[8];
#pragma unroll
    for (int j = 0; j < 8; j++) v[j] = p[tid + j * 256];

    float m = v[0];
#pragma unroll
    for (int j = 1; j < 8; j++) m = fmaxf(m, v[j]);
    m = warp_max(m);
    if ((tid & 31) == 0) red[tid >> 5] = m;
    __syncthreads();
    if (tid < 32) {
        float t = (tid < 8) ? red[tid] : -INFINITY;
        t = warp_max(t);
        if (tid == 0) red[0] = t;
    }
    __syncthreads();
    m = red[0];

    float s = 0.0f;
#pragma unroll
    for (int j = 0; j < 8; j++) { v[j] = __expf(v[j] - m); s += v[j]; }
    s = warp_sum(s);
    __syncthreads();
    if ((tid & 31) == 0) red[tid >> 5] = s;
    __syncthreads();
    if (tid < 32) {
        float t = (tid < 8) ? red[tid] : 0.0f;
        t = warp_sum(t);
        if (tid == 0) red[0] = t;
    }
    __syncthreads();
    const float inv = 1.0f / red[0];

#pragma unroll
    for (int j = 0; j < 8; j++) {
        float r = v[j] * inv;
        int col = tid + j * 256;
        p[col] = r;
        __nv_bfloat16 h = __float2bfloat16(r);
        g_ah[rowbase + col] = h;
        g_al[rowbase + col] = __float2bfloat16(r - __bfloat162float(h));
    }
}

// ---------------------------------------------------------------------------
extern "C" void kernel_launch(void* const* d_in, const int* in_sizes, int n_in,
                              void* d_out, int out_size) {
    const float* x  = (const float*)d_in[0];   // [B,S,D]
    const float* wq = (const float*)d_in[1];   // [D,U]
    const float* wk = (const float*)d_in[2];
    const float* wv = (const float*)d_in[3];

    float* out  = (float*)d_out;
    float* ctx  = out;                         // [B,S,U]
    float* attn = out + NX;                    // [B,S,S]

    cudaFuncSetAttribute(mt_kernel,      cudaFuncAttributeMaxDynamicSharedMemorySize, SMEM_DYN);
    cudaFuncSetAttribute(p_kernel,       cudaFuncAttributeMaxDynamicSharedMemorySize, SMEM_DYN);
    cudaFuncSetAttribute(v_kernel,       cudaFuncAttributeMaxDynamicSharedMemorySize, SMEM_DYN);
    cudaFuncSetAttribute(scores_kernel,  cudaFuncAttributeMaxDynamicSharedMemorySize, SMEM_DYN);
    cudaFuncSetAttribute(context_kernel, cudaFuncAttributeMaxDynamicSharedMemorySize, SMEM_DYN);

    // 1. splits: x, Wq, Wk (plain), Wv (transposed)
    split_x_kernel<<<(int)(NX / 4 / 256), 256>>>(x);
    splitW_kernel<<<dim3((int)(NW / 4 / 256), 2), 256>>>(wq, wk);
    wsplitT_kernel<<<dim3(UU / 32, DD / 32), dim3(32, 8)>>>(wv);

    // 2. Mt = scale * Wk @ Wq^T  [512x512]
    mt_kernel<<<dim3(4, 4), 256, SMEM_DYN>>>();

    // 3. P = x @ Mt^T  [16384x512], V^T = (x @ Wv)^T  [B][512][2048]
    p_kernel<<<dim3(4, 128), 256, SMEM_DYN>>>();
    v_kernel<<<dim3(4, 128), 256, SMEM_DYN>>>();

    // 4. scores = P @ x^T per batch (scale already folded into Mt)
    scores_kernel<<<dim3(16, 16, BB), 256, SMEM_DYN>>>(attn);

    // 5. softmax + bf16 hi/lo split of attn
    softmax_split_kernel<<<dim3(BB * SS), 256>>>(attn);

    // 6. context = attn @ V per batch
    context_kernel<<<dim3(4, 16, BB), 256, SMEM_DYN>>>(ctx);
}

// round 7
// speedup vs baseline: 2.6458x; 1.1822x over previous
#include <cuda_runtime.h>
#include <cuda_bf16.h>
#include <mma.h>
#include <cstdint>
#include <math.h>

using namespace nvcuda;

// Problem constants
#define BB 8
#define SS 2048
#define DD 512
#define UU 512

#define NX ((size_t)BB * SS * DD)      // 8388608
#define NW ((size_t)DD * UU)           // 262144
#define NA ((size_t)BB * SS * SS)      // 33554432

#define SCALE 0.04419417382415922f    // 1/sqrt(512)

// ---------------------------------------------------------------------------
// Device-global scratch (no allocations allowed)
// ---------------------------------------------------------------------------
__device__ __align__(128) __nv_bfloat16 g_xh[NX],  g_xl[NX];     // x splits [B*S][D]
__device__ __align__(128) __nv_bfloat16 g_wqh[NW], g_wql[NW];    // Wq splits [D][U]
__device__ __align__(128) __nv_bfloat16 g_wkh[NW], g_wkl[NW];    // Wk splits [D][U]
__device__ __align__(128) __nv_bfloat16 g_wvth[NW], g_wvtl[NW];  // Wv^T splits [U][D]
__device__ __align__(128) __nv_bfloat16 g_mth[NW], g_mtl[NW];    // Mt = scale*Wk Wq^T [D][D]
__device__ __align__(128) __nv_bfloat16 g_ph[NX],  g_pl[NX];     // P = x Mt^T [B*S][D]
__device__ __align__(128) __nv_bfloat16 g_vth[NX], g_vtl[NX];    // V^T splits [B][U][S]
__device__ __align__(128) __nv_bfloat16 g_ah[NA],  g_al[NA];     // attn splits [B][S][S]

// ---------------------------------------------------------------------------
// Helpers
// ---------------------------------------------------------------------------
__device__ __forceinline__ uint32_t smem_u32(const void* p) {
    uint32_t a;
    asm("{ .reg .u64 t; cvta.to.shared.u64 t, %1; cvt.u32.u64 %0, t; }" : "=r"(a) : "l"(p));
    return a;
}
__device__ __forceinline__ uint32_t pack_bf2(__nv_bfloat16 a, __nv_bfloat16 b) {
    return (uint32_t)__bfloat16_as_ushort(a) | ((uint32_t)__bfloat16_as_ushort(b) << 16);
}

// ---------------------------------------------------------------------------
// bf16x3 mma GEMM: 128x128 CTA tile, BK=32, 256 threads (8 warps, 2x4 grid,
// 64x32 warp tile), cp.async double buffered, 2 CTAs/SM.  ALL operands K-major:
//   A: MxK row-major (hi/lo), B: NxK row-major (hi/lo).  C = A * B^T.
// MODE 0: fp32 store to Cf.   MODE 1: alpha-scaled bf16 hi/lo split store.
// MODE 2: bf16 hi/lo split TRANSPOSED store (per-batch V^T layout, ldo = SS).
// ---------------------------------------------------------------------------
#define ARR_H 5120                      // 128 * 40 halves per array
#define STG_H 20480                     // 4 arrays per stage
#define SMEM_DYN (2 * STG_H * 2)        // bytes = 81920

__device__ __forceinline__ void stage_arr(uint32_t sdst, const __nv_bfloat16* __restrict__ src,
                                          int r0, int k0, int ld, int tid) {
#pragma unroll
    for (int j = 0; j < 2; j++) {
        int idx = tid + j * 256;                  // 512 chunks of 16B
        int r = idx >> 2, c = idx & 3;
        uint32_t dst = sdst + (uint32_t)(r * 80 + c * 16);
        const void* gp = (const void*)(src + (size_t)(r0 + r) * ld + k0 + c * 8);
        asm volatile("cp.async.cg.shared.global [%0], [%1], 16;" :: "r"(dst), "l"(gp));
    }
}

template <int MODE>
__device__ __forceinline__ void gemm_mma(int row0, int col0,
                                         const __nv_bfloat16* __restrict__ Ah,
                                         const __nv_bfloat16* __restrict__ Al,
                                         const __nv_bfloat16* __restrict__ Bh,
                                         const __nv_bfloat16* __restrict__ Bl,
                                         int K, int lda, int ldb, float alpha,
                                         float* __restrict__ Cf, int ldc,
                                         __nv_bfloat16* __restrict__ Oh,
                                         __nv_bfloat16* __restrict__ Ol, int ldo) {
    extern __shared__ __nv_bfloat16 smem[];

    const int tid  = threadIdx.x;
    const int warp = tid >> 5;
    const int lane = tid & 31;
    const int wm = (warp >> 2) * 64;     // warp row: 0 / 64
    const int wn = (warp & 3) * 32;      // warp col: 0..96

    const uint32_t sbase = smem_u32(smem);

    wmma::fragment<wmma::accumulator, 16, 16, 16, float> acc[4][2];
#pragma unroll
    for (int i = 0; i < 4; i++)
#pragma unroll
        for (int j = 0; j < 2; j++) wmma::fill_fragment(acc[i][j], 0.0f);

    const int niter = K >> 5;

    // prologue: stage iter 0 -> buf 0
    {
        uint32_t b0 = sbase;
        stage_arr(b0 + 0 * ARR_H * 2, Ah, row0, 0, lda, tid);
        stage_arr(b0 + 1 * ARR_H * 2, Al, row0, 0, lda, tid);
        stage_arr(b0 + 2 * ARR_H * 2, Bh, col0, 0, ldb, tid);
        stage_arr(b0 + 3 * ARR_H * 2, Bl, col0, 0, ldb, tid);
        asm volatile("cp.async.commit_group;" ::: "memory");
    }

    for (int it = 0; it < niter; it++) {
        const int buf = it & 1;
        if (it + 1 < niter) {
            uint32_t nb = sbase + (uint32_t)((buf ^ 1) * STG_H * 2);
            int k0 = (it + 1) << 5;
            stage_arr(nb + 0 * ARR_H * 2, Ah, row0, k0, lda, tid);
            stage_arr(nb + 1 * ARR_H * 2, Al, row0, k0, lda, tid);
            stage_arr(nb + 2 * ARR_H * 2, Bh, col0, k0, ldb, tid);
            stage_arr(nb + 3 * ARR_H * 2, Bl, col0, k0, ldb, tid);
            asm volatile("cp.async.commit_group;" ::: "memory");
            asm volatile("cp.async.wait_group 1;" ::: "memory");
        } else {
            asm volatile("cp.async.wait_group 0;" ::: "memory");
        }
        __syncthreads();

        const __nv_bfloat16* sAh = smem + buf * STG_H + 0 * ARR_H;
        const __nv_bfloat16* sAl = smem + buf * STG_H + 1 * ARR_H;
        const __nv_bfloat16* sBh = smem + buf * STG_H + 2 * ARR_H;
        const __nv_bfloat16* sBl = smem + buf * STG_H + 3 * ARR_H;

#pragma unroll
        for (int ks = 0; ks < 32; ks += 16) {
            wmma::fragment<wmma::matrix_b, 16, 16, 16, __nv_bfloat16, wmma::col_major> fbh[2], fbl[2];
#pragma unroll
            for (int j = 0; j < 2; j++) {
                wmma::load_matrix_sync(fbh[j], &sBh[(wn + j * 16) * 40 + ks], 40);
                wmma::load_matrix_sync(fbl[j], &sBl[(wn + j * 16) * 40 + ks], 40);
            }
#pragma unroll
            for (int i = 0; i < 4; i++) {
                wmma::fragment<wmma::matrix_a, 16, 16, 16, __nv_bfloat16, wmma::row_major> fah, fal;
                wmma::load_matrix_sync(fah, &sAh[(wm + i * 16) * 40 + ks], 40);
                wmma::load_matrix_sync(fal, &sAl[(wm + i * 16) * 40 + ks], 40);
#pragma unroll
                for (int j = 0; j < 2; j++) {
                    wmma::mma_sync(acc[i][j], fah, fbh[j], acc[i][j]);
                    wmma::mma_sync(acc[i][j], fah, fbl[j], acc[i][j]);
                    wmma::mma_sync(acc[i][j], fal, fbh[j], acc[i][j]);
                }
            }
        }
        __syncthreads();
    }

    // ------------------------- epilogue -------------------------
    if constexpr (MODE == 0) {
#pragma unroll
        for (int i = 0; i < 4; i++)
#pragma unroll
            for (int j = 0; j < 2; j++)
                wmma::store_matrix_sync(
                    &Cf[(size_t)(row0 + wm + i * 16) * ldc + col0 + wn + j * 16],
                    acc[i][j], ldc, wmma::mem_row_major);
    } else {
        // reuse pipeline smem for per-warp epilogue staging (pipeline is done)
        float* ew = (float*)(smem + warp * (16 * 24 * 2));
        if constexpr (MODE == 1) {
#pragma unroll
            for (int i = 0; i < 4; i++)
#pragma unroll
                for (int j = 0; j < 2; j++) {
                    wmma::store_matrix_sync(ew, acc[i][j], 24, wmma::mem_row_major);
                    __syncwarp();
                    int r = lane >> 1, cb = (lane & 1) * 8;
                    float v[8];
#pragma unroll
                    for (int e = 0; e < 8; e++) v[e] = ew[r * 24 + cb + e] * alpha;
                    uint4 hp, lp;
                    __nv_bfloat16 h[8];
#pragma unroll
                    for (int e = 0; e < 8; e++) h[e] = __float2bfloat16(v[e]);
                    hp.x = pack_bf2(h[0], h[1]); hp.y = pack_bf2(h[2], h[3]);
                    hp.z = pack_bf2(h[4], h[5]); hp.w = pack_bf2(h[6], h[7]);
                    __nv_bfloat16 l[8];
#pragma unroll
                    for (int e = 0; e < 8; e++) l[e] = __float2bfloat16(v[e] - __bfloat162float(h[e]));
                    lp.x = pack_bf2(l[0], l[1]); lp.y = pack_bf2(l[2], l[3]);
                    lp.z = pack_bf2(l[4], l[5]); lp.w = pack_bf2(l[6], l[7]);
                    size_t idx = (size_t)(row0 + wm + i * 16 + r) * ldo + col0 + wn + j * 16 + cb;
                    *reinterpret_cast<uint4*>(&Oh[idx]) = hp;
                    *reinterpret_cast<uint4*>(&Ol[idx]) = lp;
                    __syncwarp();
                }
        } else {
            // MODE 2: transposed split (V^T), row0 indexes tokens [B*S]
            const int b  = row0 >> 11;               // SS == 2048
            const int s0 = (row0 & 2047) + wm;
            __nv_bfloat16* ohb = Oh + (size_t)b * UU * SS;
            __nv_bfloat16* olb = Ol + (size_t)b * UU * SS;
#pragma unroll
            for (int i = 0; i < 4; i++)
#pragma unroll
                for (int j = 0; j < 2; j++) {
                    wmma::store_matrix_sync(ew, acc[i][j], 24, wmma::mem_row_major);
                    __syncwarp();
                    if (lane < 16) {
                        int u = lane;
                        float v[16];
#pragma unroll
                        for (int r = 0; r < 16; r++) v[r] = ew[r * 24 + u];
                        uint32_t hw[8], lw[8];
#pragma unroll
                        for (int e = 0; e < 8; e++) {
                            __nv_bfloat16 ha = __float2bfloat16(v[2 * e]);
                            __nv_bfloat16 hb = __float2bfloat16(v[2 * e + 1]);
                            hw[e] = pack_bf2(ha, hb);
                            lw[e] = pack_bf2(__float2bfloat16(v[2 * e] - __bfloat162float(ha)),
                                             __float2bfloat16(v[2 * e + 1] - __bfloat162float(hb)));
                        }
                        size_t idx = (size_t)(col0 + wn + j * 16 + u) * SS + s0 + i * 16;
                        uint4 h0, h1, l0, l1;
                        h0.x = hw[0]; h0.y = hw[1]; h0.z = hw[2]; h0.w = hw[3];
                        h1.x = hw[4]; h1.y = hw[5]; h1.z = hw[6]; h1.w = hw[7];
                        l0.x = lw[0]; l0.y = lw[1]; l0.z = lw[2]; l0.w = lw[3];
                        l1.x = lw[4]; l1.y = lw[5]; l1.z = lw[6]; l1.w = lw[7];
                        *reinterpret_cast<uint4*>(&ohb[idx])     = h0;
                        *reinterpret_cast<uint4*>(&ohb[idx + 8]) = h1;
                        *reinterpret_cast<uint4*>(&olb[idx])     = l0;
                        *reinterpret_cast<uint4*>(&olb[idx + 8]) = l1;
                    }
                    __syncwarp();
                }
        }
    }
}

// ---------------------------------------------------------------------------
// GEMM kernel wrappers (all forced to 2 CTAs/SM)
// ---------------------------------------------------------------------------

// Combined V^T projection (blocks 0..511) + Mt (blocks 512..527).
__global__ __launch_bounds__(256, 2) void vmt_kernel() {
    int id = blockIdx.x;
    if (id < 512) {
        int row0 = (id >> 2) * 128;       // token tile
        int col0 = (id & 3) * 128;        // u tile
        gemm_mma<2>(row0, col0, g_xh, g_xl, g_wvth, g_wvtl, DD, DD, DD, 1.0f,
                    nullptr, 0, g_vth, g_vtl, SS);
    } else {
        int id2 = id - 512;
        int row0 = (id2 >> 2) * 128;
        int col0 = (id2 & 3) * 128;
        gemm_mma<1>(row0, col0, g_wkh, g_wkl, g_wqh, g_wql, UU, UU, UU, SCALE,
                    nullptr, 0, g_mth, g_mtl, DD);
    }
}

__global__ __launch_bounds__(256, 2) void p_kernel() {
    // P = x @ Mt^T  -> [B*S][D] split
    gemm_mma<1>(blockIdx.y * 128, blockIdx.x * 128,
                g_xh, g_xl, g_mth, g_mtl, DD, DD, DD, 1.0f,
                nullptr, 0, g_ph, g_pl, DD);
}

__global__ __launch_bounds__(256, 2) void scores_kernel(float* __restrict__ attn) {
    const size_t zo = (size_t)blockIdx.z * SS * DD;
    gemm_mma<0>(blockIdx.y * 128, blockIdx.x * 128,
                g_ph + zo, g_pl + zo, g_xh + zo, g_xl + zo, DD, DD, DD, 1.0f,
                attn + (size_t)blockIdx.z * SS * SS, SS, nullptr, nullptr, 0);
}

__global__ __launch_bounds__(256, 2) void context_kernel(float* __restrict__ ctx) {
    const size_t z = blockIdx.z;
    gemm_mma<0>(blockIdx.y * 128, blockIdx.x * 128,
                g_ah + z * (size_t)SS * SS, g_al + z * (size_t)SS * SS,
                g_vth + z * (size_t)UU * SS, g_vtl + z * (size_t)UU * SS,
                SS, SS, SS, 1.0f,
                ctx + z * (size_t)SS * UU, UU, nullptr, nullptr, 0);
}

// ---------------------------------------------------------------------------
// Elementwise kernels
// ---------------------------------------------------------------------------
__global__ __launch_bounds__(256) void split_x_kernel(const float* __restrict__ in) {
    int i = blockIdx.x * 256 + threadIdx.x;     // float4 granules, NX/4 total
    float4 v = reinterpret_cast<const float4*>(in)[i];
    __nv_bfloat16 h0 = __float2bfloat16(v.x), h1 = __float2bfloat16(v.y);
    __nv_bfloat16 h2 = __float2bfloat16(v.z), h3 = __float2bfloat16(v.w);
    uint2 hp, lp;
    hp.x = pack_bf2(h0, h1); hp.y = pack_bf2(h2, h3);
    lp.x = pack_bf2(__float2bfloat16(v.x - __bfloat162float(h0)),
                    __float2bfloat16(v.y - __bfloat162float(h1)));
    lp.y = pack_bf2(__float2bfloat16(v.z - __bfloat162float(h2)),
                    __float2bfloat16(v.w - __bfloat162float(h3)));
    reinterpret_cast<uint2*>(g_xh)[i] = hp;
    reinterpret_cast<uint2*>(g_xl)[i] = lp;
}

__global__ __launch_bounds__(256) void splitW_kernel(const float* __restrict__ wq,
                                                     const float* __restrict__ wk) {
    const float* src = (blockIdx.y == 0) ? wq : wk;
    __nv_bfloat16* oh = (blockIdx.y == 0) ? g_wqh : g_wkh;
    __nv_bfloat16* ol = (blockIdx.y == 0) ? g_wql : g_wkl;
    int i = blockIdx.x * 256 + threadIdx.x;     // NW/4 granules
    float4 v = reinterpret_cast<const float4*>(src)[i];
    __nv_bfloat16 h0 = __float2bfloat16(v.x), h1 = __float2bfloat16(v.y);
    __nv_bfloat16 h2 = __float2bfloat16(v.z), h3 = __float2bfloat16(v.w);
    uint2 hp, lp;
    hp.x = pack_bf2(h0, h1); hp.y = pack_bf2(h2, h3);
    lp.x = pack_bf2(__float2bfloat16(v.x - __bfloat162float(h0)),
                    __float2bfloat16(v.y - __bfloat162float(h1)));
    lp.y = pack_bf2(__float2bfloat16(v.z - __bfloat162float(h2)),
                    __float2bfloat16(v.w - __bfloat162float(h3)));
    reinterpret_cast<uint2*>(oh)[i] = hp;
    reinterpret_cast<uint2*>(ol)[i] = lp;
}

__global__ void wsplitT_kernel(const float* __restrict__ wv) {
    __shared__ float t[32][33];
    const int u0 = blockIdx.x * 32, d0 = blockIdx.y * 32;
    const int tx = threadIdx.x, ty = threadIdx.y;
#pragma unroll
    for (int p = 0; p < 4; p++)
        t[ty + p * 8][tx] = wv[(size_t)(d0 + ty + p * 8) * UU + u0 + tx];
    __syncthreads();
#pragma unroll
    for (int p = 0; p < 4; p++) {
        float v = t[tx][ty + p * 8];
        __nv_bfloat16 h = __float2bfloat16(v);
        size_t idx = (size_t)(u0 + ty + p * 8) * DD + d0 + tx;
        g_wvth[idx] = h;
        g_wvtl[idx] = __float2bfloat16(v - __bfloat162float(h));
    }
}

__device__ __forceinline__ float warp_max(float v) {
#pragma unroll
    for (int o = 16; o > 0; o >>= 1) v = fmaxf(v, __shfl_xor_sync(0xffffffffu, v, o));
    return v;
}
__device__ __forceinline__ float warp_sum(float v) {
#pragma unroll
    for (int o = 16; o > 0; o >>= 1) v += __shfl_xor_sync(0xffffffffu, v, o);
    return v;
}

__global__ __launch_bounds__(256) void softmax_split_kernel(float* __restrict__ attn) {
    const size_t rowbase = (size_t)blockIdx.x * SS;
    float* p = attn + rowbase;
    const int tid = threadIdx.x;
    __shared__ float red[8];

    float v[8];
#pragma unroll
    for (int j = 0; j < 8; j++) v[j] = p[tid + j * 256];

    float m = v[0];
#pragma unroll
    for (int j = 1; j < 8; j++) m = fmaxf(m, v[j]);
    m = warp_max(m);
    if ((tid & 31) == 0) red[tid >> 5] = m;
    __syncthreads();
    if (tid < 32) {
        float t = (tid < 8) ? red[tid] : -INFINITY;
        t = warp_max(t);
        if (tid == 0) red[0] = t;
    }
    __syncthreads();
    m = red[0];

    float s = 0.0f;
#pragma unroll
    for (int j = 0; j < 8; j++) { v[j] = __expf(v[j] - m); s += v[j]; }
    s = warp_sum(s);
    __syncthreads();
    if ((tid & 31) == 0) red[tid >> 5] = s;
    __syncthreads();
    if (tid < 32) {
        float t = (tid < 8) ? red[tid] : 0.0f;
        t = warp_sum(t);
        if (tid == 0) red[0] = t;
    }
    __syncthreads();
    const float inv = 1.0f / red[0];

#pragma unroll
    for (int j = 0; j < 8; j++) {
        float r = v[j] * inv;
        int col = tid + j * 256;
        p[col] = r;
        __nv_bfloat16 h = __float2bfloat16(r);
        g_ah[rowbase + col] = h;
        g_al[rowbase + col] = __float2bfloat16(r - __bfloat162float(h));
    }
}

// ---------------------------------------------------------------------------
extern "C" void kernel_launch(void* const* d_in, const int* in_sizes, int n_in,
                              void* d_out, int out_size) {
    const float* x  = (const float*)d_in[0];   // [B,S,D]
    const float* wq = (const float*)d_in[1];   // [D,U]
    const float* wk = (const float*)d_in[2];
    const float* wv = (const float*)d_in[3];

    float* out  = (float*)d_out;
    float* ctx  = out;                         // [B,S,U]
    float* attn = out + NX;                    // [B,S,S]

    cudaFuncSetAttribute(vmt_kernel,     cudaFuncAttributeMaxDynamicSharedMemorySize, SMEM_DYN);
    cudaFuncSetAttribute(p_kernel,       cudaFuncAttributeMaxDynamicSharedMemorySize, SMEM_DYN);
    cudaFuncSetAttribute(scores_kernel,  cudaFuncAttributeMaxDynamicSharedMemorySize, SMEM_DYN);
    cudaFuncSetAttribute(context_kernel, cudaFuncAttributeMaxDynamicSharedMemorySize, SMEM_DYN);

    // 1. splits: x, Wq, Wk (plain), Wv (transposed)
    split_x_kernel<<<(int)(NX / 4 / 256), 256>>>(x);
    splitW_kernel<<<dim3((int)(NW / 4 / 256), 2), 256>>>(wq, wk);
    wsplitT_kernel<<<dim3(UU / 32, DD / 32), dim3(32, 8)>>>(wv);

    // 2. V^T = (x @ Wv)^T  and  Mt = scale * Wk @ Wq^T  (one launch)
    vmt_kernel<<<dim3(528), 256, SMEM_DYN>>>();

    // 3. P = x @ Mt^T  [16384x512]
    p_kernel<<<dim3(4, 128), 256, SMEM_DYN>>>();

    // 4. scores = P @ x^T per batch (scale already folded into Mt)
    scores_kernel<<<dim3(16, 16, BB), 256, SMEM_DYN>>>(attn);

    // 5. softmax + bf16 hi/lo split of attn
    softmax_split_kernel<<<dim3(BB * SS), 256>>>(attn);

    // 6. context = attn @ V per batch
    context_kernel<<<dim3(4, 16, BB), 256, SMEM_DYN>>>(ctx);
}

// round 8
// speedup vs baseline: 2.9641x; 1.1203x over previous
#include <cuda_runtime.h>
#include <cuda_bf16.h>
#include <cstdint>
#include <math.h>

// Problem constants
#define BB 8
#define SS 2048
#define DD 512
#define UU 512

#define NX ((size_t)BB * SS * DD)      // 8388608
#define NW ((size_t)DD * UU)           // 262144
#define NA ((size_t)BB * SS * SS)      // 33554432

#define SCALE 0.04419417382415922f    // 1/sqrt(512)

// ---------------------------------------------------------------------------
// Device-global scratch (no allocations allowed)
// ---------------------------------------------------------------------------
__device__ __align__(128) __nv_bfloat16 g_xh[NX],  g_xl[NX];     // x splits [B*S][D]
__device__ __align__(128) __nv_bfloat16 g_wqh[NW], g_wql[NW];    // Wq splits [D][U]
__device__ __align__(128) __nv_bfloat16 g_wkh[NW], g_wkl[NW];    // Wk splits [D][U]
__device__ __align__(128) __nv_bfloat16 g_wvth[NW], g_wvtl[NW];  // Wv^T splits [U][D]
__device__ __align__(128) __nv_bfloat16 g_mth[NW], g_mtl[NW];    // Mt = scale*Wk Wq^T [D][D]
__device__ __align__(128) __nv_bfloat16 g_ph[NX],  g_pl[NX];     // P = x Mt^T [B*S][D]
__device__ __align__(128) __nv_bfloat16 g_vth[NX], g_vtl[NX];    // V^T splits [B][U][S]
__device__ __align__(128) __nv_bfloat16 g_ah[NA],  g_al[NA];     // attn splits [B][S][S]

// ---------------------------------------------------------------------------
// Helpers
// ---------------------------------------------------------------------------
__device__ __forceinline__ uint32_t smem_u32(const void* p) {
    uint32_t a;
    asm("{ .reg .u64 t; cvta.to.shared.u64 t, %1; cvt.u32.u64 %0, t; }" : "=r"(a) : "l"(p));
    return a;
}
__device__ __forceinline__ uint32_t pack_bf2(__nv_bfloat16 a, __nv_bfloat16 b) {
    return (uint32_t)__bfloat16_as_ushort(a) | ((uint32_t)__bfloat16_as_ushort(b) << 16);
}

#define LDSM4(r0, r1, r2, r3, addr) \
    asm volatile("ldmatrix.sync.aligned.m8n8.x4.shared.b16 {%0,%1,%2,%3}, [%4];" \
        : "=r"(r0), "=r"(r1), "=r"(r2), "=r"(r3) : "r"(addr))

#define MMA16816(d, a, b) \
    asm volatile("mma.sync.aligned.m16n8k16.row.col.f32.bf16.bf16.f32 " \
        "{%0,%1,%2,%3}, {%4,%5,%6,%7}, {%8,%9}, {%0,%1,%2,%3};" \
        : "+f"((d)[0]), "+f"((d)[1]), "+f"((d)[2]), "+f"((d)[3]) \
        : "r"((a)[0]), "r"((a)[1]), "r"((a)[2]), "r"((a)[3]), \
          "r"((b)[0]), "r"((b)[1]))

// ---------------------------------------------------------------------------
// bf16x3 mma GEMM: 128x128 CTA tile, BK=32, 256 threads (8 warps, 2x4 grid,
// 64x32 warp tile), cp.async double buffered, 2 CTAs/SM.  ALL operands K-major:
//   A: MxK row-major (hi/lo), B: NxK row-major (hi/lo).  C = A * B^T.
// Raw mma.sync core: per k16 step load all frags, then issue MMAs term-major
// (hh*16, hl*16, lh*16) so consecutive MMAs never share an accumulator.
// MODE 0: fp32 store to Cf.   MODE 1: alpha-scaled bf16 hi/lo split store.
// MODE 2: bf16 hi/lo split TRANSPOSED store (per-batch V^T layout).
// ---------------------------------------------------------------------------
#define ARR_B 10240                     // 128 rows * 80 bytes per array
#define STG_B 40960                     // 4 arrays per stage
#define SMEM_DYN (2 * STG_B)            // 81920 bytes

__device__ __forceinline__ void stage_arr(uint32_t sdst, const __nv_bfloat16* __restrict__ src,
                                          int r0, int k0, int ld, int tid) {
#pragma unroll
    for (int j = 0; j < 2; j++) {
        int idx = tid + j * 256;                  // 512 chunks of 16B
        int r = idx >> 2, c = idx & 3;
        uint32_t dst = sdst + (uint32_t)(r * 80 + c * 16);
        const void* gp = (const void*)(src + (size_t)(r0 + r) * ld + k0 + c * 8);
        asm volatile("cp.async.cg.shared.global [%0], [%1], 16;" :: "r"(dst), "l"(gp));
    }
}

template <int MODE>
__device__ __forceinline__ void gemm_mma(int row0, int col0,
                                         const __nv_bfloat16* __restrict__ Ah,
                                         const __nv_bfloat16* __restrict__ Al,
                                         const __nv_bfloat16* __restrict__ Bh,
                                         const __nv_bfloat16* __restrict__ Bl,
                                         int K, int lda, int ldb, float alpha,
                                         float* __restrict__ Cf, int ldc,
                                         __nv_bfloat16* __restrict__ Oh,
                                         __nv_bfloat16* __restrict__ Ol, int ldo) {
    extern __shared__ __nv_bfloat16 smem[];

    const int tid  = threadIdx.x;
    const int warp = tid >> 5;
    const int lane = tid & 31;
    const int wm = (warp >> 2) * 64;     // warp row: 0 / 64
    const int wn = (warp & 3) * 32;      // warp col: 0..96

    const uint32_t sbase = smem_u32(smem);

    // Per-lane ldmatrix byte offsets within an array (before i/jp/ks offsets).
    // A x4 matrices: (m0-7,klo),(m8-15,klo),(m0-7,khi),(m8-15,khi)
    const uint32_t aLane = (uint32_t)((wm + ((lane >> 3) & 1) * 8 + (lane & 7)) * 80
                                      + (lane >> 4) * 16);
    // B x4 matrices: (n0-7,klo),(n0-7,khi),(n8-15,klo),(n8-15,khi)
    const uint32_t bLane = (uint32_t)((wn + ((lane >> 4) & 1) * 8 + (lane & 7)) * 80
                                      + ((lane >> 3) & 1) * 16);

    float acc[4][4][4];                  // [i m16][j n8][4]
#pragma unroll
    for (int i = 0; i < 4; i++)
#pragma unroll
        for (int j = 0; j < 4; j++)
#pragma unroll
            for (int e = 0; e < 4; e++) acc[i][j][e] = 0.0f;

    const int niter = K >> 5;

    // prologue: stage iter 0 -> buf 0
    {
        stage_arr(sbase + 0 * ARR_B, Ah, row0, 0, lda, tid);
        stage_arr(sbase + 1 * ARR_B, Al, row0, 0, lda, tid);
        stage_arr(sbase + 2 * ARR_B, Bh, col0, 0, ldb, tid);
        stage_arr(sbase + 3 * ARR_B, Bl, col0, 0, ldb, tid);
        asm volatile("cp.async.commit_group;" ::: "memory");
    }

    for (int it = 0; it < niter; it++) {
        const int buf = it & 1;
        if (it + 1 < niter) {
            uint32_t nb = sbase + (uint32_t)((buf ^ 1) * STG_B);
            int k0 = (it + 1) << 5;
            stage_arr(nb + 0 * ARR_B, Ah, row0, k0, lda, tid);
            stage_arr(nb + 1 * ARR_B, Al, row0, k0, lda, tid);
            stage_arr(nb + 2 * ARR_B, Bh, col0, k0, ldb, tid);
            stage_arr(nb + 3 * ARR_B, Bl, col0, k0, ldb, tid);
            asm volatile("cp.async.commit_group;" ::: "memory");
            asm volatile("cp.async.wait_group 1;" ::: "memory");
        } else {
            asm volatile("cp.async.wait_group 0;" ::: "memory");
        }
        __syncthreads();

        const uint32_t base = sbase + (uint32_t)(buf * STG_B);
        const uint32_t pAh = base + 0 * ARR_B + aLane;
        const uint32_t pAl = base + 1 * ARR_B + aLane;
        const uint32_t pBh = base + 2 * ARR_B + bLane;
        const uint32_t pBl = base + 3 * ARR_B + bLane;

#pragma unroll
        for (int ks = 0; ks < 2; ks++) {
            const uint32_t ko = ks * 32;         // 16 halves = 32 bytes
            uint32_t ah[4][4], al[4][4];         // [i][reg]
            uint32_t bh[4][2], bl[4][2];         // [j][reg]
#pragma unroll
            for (int jp = 0; jp < 2; jp++) {
                LDSM4(bh[2 * jp][0], bh[2 * jp][1], bh[2 * jp + 1][0], bh[2 * jp + 1][1],
                      pBh + jp * 1280 + ko);
                LDSM4(bl[2 * jp][0], bl[2 * jp][1], bl[2 * jp + 1][0], bl[2 * jp + 1][1],
                      pBl + jp * 1280 + ko);
            }
#pragma unroll
            for (int i = 0; i < 4; i++) {
                LDSM4(ah[i][0], ah[i][1], ah[i][2], ah[i][3], pAh + i * 1280 + ko);
                LDSM4(al[i][0], al[i][1], al[i][2], al[i][3], pAl + i * 1280 + ko);
            }
            // term-major MMA issue: no consecutive same-accumulator ops
#pragma unroll
            for (int i = 0; i < 4; i++)
#pragma unroll
                for (int j = 0; j < 4; j++) MMA16816(acc[i][j], ah[i], bh[j]);
#pragma unroll
            for (int i = 0; i < 4; i++)
#pragma unroll
                for (int j = 0; j < 4; j++) MMA16816(acc[i][j], ah[i], bl[j]);
#pragma unroll
            for (int i = 0; i < 4; i++)
#pragma unroll
                for (int j = 0; j < 4; j++) MMA16816(acc[i][j], al[i], bh[j]);
        }
        __syncthreads();
    }

    // ------------------------- epilogue -------------------------
    // acc frag layout: thread t: c0:(m=t/4, n=2(t%4)) c1:(m, n+1) c2:(m+8, n) c3:(m+8, n+1)
    const int er = lane >> 2;
    const int ec = (lane & 3) * 2;

    if constexpr (MODE == 0) {
#pragma unroll
        for (int i = 0; i < 4; i++)
#pragma unroll
            for (int j = 0; j < 4; j++) {
                size_t r = (size_t)(row0 + wm + i * 16 + er);
                int c = col0 + wn + j * 8 + ec;
                *reinterpret_cast<float2*>(&Cf[r * ldc + c]) =
                    make_float2(acc[i][j][0], acc[i][j][1]);
                *reinterpret_cast<float2*>(&Cf[(r + 8) * ldc + c]) =
                    make_float2(acc[i][j][2], acc[i][j][3]);
            }
    } else {
        // stage 16x16 subtiles (i, jp) through per-warp smem, then split-store
        float* ew = (float*)(smem + warp * 768);   // 16x24 floats = 1536 B per warp
        if constexpr (MODE == 1) {
#pragma unroll
            for (int i = 0; i < 4; i++)
#pragma unroll
                for (int jp = 0; jp < 2; jp++) {
                    int j0 = 2 * jp, j1 = 2 * jp + 1;
                    ew[er * 24 + ec]            = acc[i][j0][0];
                    ew[er * 24 + ec + 1]        = acc[i][j0][1];
                    ew[(er + 8) * 24 + ec]      = acc[i][j0][2];
                    ew[(er + 8) * 24 + ec + 1]  = acc[i][j0][3];
                    ew[er * 24 + 8 + ec]        = acc[i][j1][0];
                    ew[er * 24 + 8 + ec + 1]    = acc[i][j1][1];
                    ew[(er + 8) * 24 + 8 + ec]     = acc[i][j1][2];
                    ew[(er + 8) * 24 + 8 + ec + 1] = acc[i][j1][3];
                    __syncwarp();
                    int r = lane >> 1, cb = (lane & 1) * 8;
                    float v[8];
#pragma unroll
                    for (int e = 0; e < 8; e++) v[e] = ew[r * 24 + cb + e] * alpha;
                    uint4 hp, lp;
                    __nv_bfloat16 h[8];
#pragma unroll
                    for (int e = 0; e < 8; e++) h[e] = __float2bfloat16(v[e]);
                    hp.x = pack_bf2(h[0], h[1]); hp.y = pack_bf2(h[2], h[3]);
                    hp.z = pack_bf2(h[4], h[5]); hp.w = pack_bf2(h[6], h[7]);
                    __nv_bfloat16 l[8];
#pragma unroll
                    for (int e = 0; e < 8; e++) l[e] = __float2bfloat16(v[e] - __bfloat162float(h[e]));
                    lp.x = pack_bf2(l[0], l[1]); lp.y = pack_bf2(l[2], l[3]);
                    lp.z = pack_bf2(l[4], l[5]); lp.w = pack_bf2(l[6], l[7]);
                    size_t idx = (size_t)(row0 + wm + i * 16 + r) * ldo + col0 + wn + jp * 16 + cb;
                    *reinterpret_cast<uint4*>(&Oh[idx]) = hp;
                    *reinterpret_cast<uint4*>(&Ol[idx]) = lp;
                    __syncwarp();
                }
        } else {
            // MODE 2: transposed split (V^T), row0 indexes tokens [B*S]
            const int b  = row0 >> 11;               // SS == 2048
            const int s0 = (row0 & 2047) + wm;
            __nv_bfloat16* ohb = Oh + (size_t)b * UU * SS;
            __nv_bfloat16* olb = Ol + (size_t)b * UU * SS;
#pragma unroll
            for (int i = 0; i < 4; i++)
#pragma unroll
                for (int jp = 0; jp < 2; jp++) {
                    int j0 = 2 * jp, j1 = 2 * jp + 1;
                    ew[er * 24 + ec]            = acc[i][j0][0];
                    ew[er * 24 + ec + 1]        = acc[i][j0][1];
                    ew[(er + 8) * 24 + ec]      = acc[i][j0][2];
                    ew[(er + 8) * 24 + ec + 1]  = acc[i][j0][3];
                    ew[er * 24 + 8 + ec]        = acc[i][j1][0];
                    ew[er * 24 + 8 + ec + 1]    = acc[i][j1][1];
                    ew[(er + 8) * 24 + 8 + ec]     = acc[i][j1][2];
                    ew[(er + 8) * 24 + 8 + ec + 1] = acc[i][j1][3];
                    __syncwarp();
                    if (lane < 16) {
                        int u = lane;
                        float v[16];
#pragma unroll
                        for (int r = 0; r < 16; r++) v[r] = ew[r * 24 + u];
                        uint32_t hw[8], lw[8];
#pragma unroll
                        for (int e = 0; e < 8; e++) {
                            __nv_bfloat16 ha = __float2bfloat16(v[2 * e]);
                            __nv_bfloat16 hb = __float2bfloat16(v[2 * e + 1]);
                            hw[e] = pack_bf2(ha, hb);
                            lw[e] = pack_bf2(__float2bfloat16(v[2 * e] - __bfloat162float(ha)),
                                             __float2bfloat16(v[2 * e + 1] - __bfloat162float(hb)));
                        }
                        size_t idx = (size_t)(col0 + wn + jp * 16 + u) * SS + s0 + i * 16;
                        uint4 h0, h1, l0, l1;
                        h0.x = hw[0]; h0.y = hw[1]; h0.z = hw[2]; h0.w = hw[3];
                        h1.x = hw[4]; h1.y = hw[5]; h1.z = hw[6]; h1.w = hw[7];
                        l0.x = lw[0]; l0.y = lw[1]; l0.z = lw[2]; l0.w = lw[3];
                        l1.x = lw[4]; l1.y = lw[5]; l1.z = lw[6]; l1.w = lw[7];
                        *reinterpret_cast<uint4*>(&ohb[idx])     = h0;
                        *reinterpret_cast<uint4*>(&ohb[idx + 8]) = h1;
                        *reinterpret_cast<uint4*>(&olb[idx])     = l0;
                        *reinterpret_cast<uint4*>(&olb[idx + 8]) = l1;
                    }
                    __syncwarp();
                }
        }
    }
}

// ---------------------------------------------------------------------------
// GEMM kernel wrappers (all forced to 2 CTAs/SM)
// ---------------------------------------------------------------------------

// Combined V^T projection (blocks 0..511) + Mt (blocks 512..527).
__global__ __launch_bounds__(256, 2) void vmt_kernel() {
    int id = blockIdx.x;
    if (id < 512) {
        int row0 = (id >> 2) * 128;       // token tile
        int col0 = (id & 3) * 128;        // u tile
        gemm_mma<2>(row0, col0, g_xh, g_xl, g_wvth, g_wvtl, DD, DD, DD, 1.0f,
                    nullptr, 0, g_vth, g_vtl, SS);
    } else {
        int id2 = id - 512;
        int row0 = (id2 >> 2) * 128;
        int col0 = (id2 & 3) * 128;
        gemm_mma<1>(row0, col0, g_wkh, g_wkl, g_wqh, g_wql, UU, UU, UU, SCALE,
                    nullptr, 0, g_mth, g_mtl, DD);
    }
}

__global__ __launch_bounds__(256, 2) void p_kernel() {
    // P = x @ Mt^T  -> [B*S][D] split
    gemm_mma<1>(blockIdx.y * 128, blockIdx.x * 128,
                g_xh, g_xl, g_mth, g_mtl, DD, DD, DD, 1.0f,
                nullptr, 0, g_ph, g_pl, DD);
}

__global__ __launch_bounds__(256, 2) void scores_kernel(float* __restrict__ attn) {
    const size_t zo = (size_t)blockIdx.z * SS * DD;
    gemm_mma<0>(blockIdx.y * 128, blockIdx.x * 128,
                g_ph + zo, g_pl + zo, g_xh + zo, g_xl + zo, DD, DD, DD, 1.0f,
                attn + (size_t)blockIdx.z * SS * SS, SS, nullptr, nullptr, 0);
}

__global__ __launch_bounds__(256, 2) void context_kernel(float* __restrict__ ctx) {
    const size_t z = blockIdx.z;
    gemm_mma<0>(blockIdx.y * 128, blockIdx.x * 128,
                g_ah + z * (size_t)SS * SS, g_al + z * (size_t)SS * SS,
                g_vth + z * (size_t)UU * SS, g_vtl + z * (size_t)UU * SS,
                SS, SS, SS, 1.0f,
                ctx + z * (size_t)SS * UU, UU, nullptr, nullptr, 0);
}

// ---------------------------------------------------------------------------
// Elementwise kernels
// ---------------------------------------------------------------------------
__global__ __launch_bounds__(256) void split_x_kernel(const float* __restrict__ in) {
    int i = blockIdx.x * 256 + threadIdx.x;     // float4 granules, NX/4 total
    float4 v = reinterpret_cast<const float4*>(in)[i];
    __nv_bfloat16 h0 = __float2bfloat16(v.x), h1 = __float2bfloat16(v.y);
    __nv_bfloat16 h2 = __float2bfloat16(v.z), h3 = __float2bfloat16(v.w);
    uint2 hp, lp;
    hp.x = pack_bf2(h0, h1); hp.y = pack_bf2(h2, h3);
    lp.x = pack_bf2(__float2bfloat16(v.x - __bfloat162float(h0)),
                    __float2bfloat16(v.y - __bfloat162float(h1)));
    lp.y = pack_bf2(__float2bfloat16(v.z - __bfloat162float(h2)),
                    __float2bfloat16(v.w - __bfloat162float(h3)));
    reinterpret_cast<uint2*>(g_xh)[i] = hp;
    reinterpret_cast<uint2*>(g_xl)[i] = lp;
}

__global__ __launch_bounds__(256) void splitW_kernel(const float* __restrict__ wq,
                                                     const float* __restrict__ wk) {
    const float* src = (blockIdx.y == 0) ? wq : wk;
    __nv_bfloat16* oh = (blockIdx.y == 0) ? g_wqh : g_wkh;
    __nv_bfloat16* ol = (blockIdx.y == 0) ? g_wql : g_wkl;
    int i = blockIdx.x * 256 + threadIdx.x;     // NW/4 granules
    float4 v = reinterpret_cast<const float4*>(src)[i];
    __nv_bfloat16 h0 = __float2bfloat16(v.x), h1 = __float2bfloat16(v.y);
    __nv_bfloat16 h2 = __float2bfloat16(v.z), h3 = __float2bfloat16(v.w);
    uint2 hp, lp;
    hp.x = pack_bf2(h0, h1); hp.y = pack_bf2(h2, h3);
    lp.x = pack_bf2(__float2bfloat16(v.x - __bfloat162float(h0)),
                    __float2bfloat16(v.y - __bfloat162float(h1)));
    lp.y = pack_bf2(__float2bfloat16(v.z - __bfloat162float(h2)),
                    __float2bfloat16(v.w - __bfloat162float(h3)));
    reinterpret_cast<uint2*>(oh)[i] = hp;
    reinterpret_cast<uint2*>(ol)[i] = lp;
}

__global__ void wsplitT_kernel(const float* __restrict__ wv) {
    __shared__ float t[32][33];
    const int u0 = blockIdx.x * 32, d0 = blockIdx.y * 32;
    const int tx = threadIdx.x, ty = threadIdx.y;
#pragma unroll
    for (int p = 0; p < 4; p++)
        t[ty + p * 8][tx] = wv[(size_t)(d0 + ty + p * 8) * UU + u0 + tx];
    __syncthreads();
#pragma unroll
    for (int p = 0; p < 4; p++) {
        float v = t[tx][ty + p * 8];
        __nv_bfloat16 h = __float2bfloat16(v);
        size_t idx = (size_t)(u0 + ty + p * 8) * DD + d0 + tx;
        g_wvth[idx] = h;
        g_wvtl[idx] = __float2bfloat16(v - __bfloat162float(h));
    }
}

__device__ __forceinline__ float warp_max(float v) {
#pragma unroll
    for (int o = 16; o > 0; o >>= 1) v = fmaxf(v, __shfl_xor_sync(0xffffffffu, v, o));
    return v;
}
__device__ __forceinline__ float warp_sum(float v) {
#pragma unroll
    for (int o = 16; o > 0; o >>= 1) v += __shfl_xor_sync(0xffffffffu, v, o);
    return v;
}

__global__ __launch_bounds__(256) void softmax_split_kernel(float* __restrict__ attn) {
    const size_t rowbase = (size_t)blockIdx.x * SS;
    float* p = attn + rowbase;
    const int tid = threadIdx.x;
    __shared__ float red[8];

    float v[8];
#pragma unroll
    for (int j = 0; j < 8; j++) v[j] = p[tid + j * 256];

    float m = v[0];
#pragma unroll
    for (int j = 1; j < 8; j++) m = fmaxf(m, v[j]);
    m = warp_max(m);
    if ((tid & 31) == 0) red[tid >> 5] = m;
    __syncthreads();
    if (tid < 32) {
        float t = (tid < 8) ? red[tid] : -INFINITY;
        t = warp_max(t);
        if (tid == 0) red[0] = t;
    }
    __syncthreads();
    m = red[0];

    float s = 0.0f;
#pragma unroll
    for (int j = 0; j < 8; j++) { v[j] = __expf(v[j] - m); s += v[j]; }
    s = warp_sum(s);
    __syncthreads();
    if ((tid & 31) == 0) red[tid >> 5] = s;
    __syncthreads();
    if (tid < 32) {
        float t = (tid < 8) ? red[tid] : 0.0f;
        t = warp_sum(t);
        if (tid == 0) red[0] = t;
    }
    __syncthreads();
    const float inv = 1.0f / red[0];

#pragma unroll
    for (int j = 0; j < 8; j++) {
        float r = v[j] * inv;
        int col = tid + j * 256;
        p[col] = r;
        __nv_bfloat16 h = __float2bfloat16(r);
        g_ah[rowbase + col] = h;
        g_al[rowbase + col] = __float2bfloat16(r - __bfloat162float(h));
    }
}

// ---------------------------------------------------------------------------
extern "C" void kernel_launch(void* const* d_in, const int* in_sizes, int n_in,
                              void* d_out, int out_size) {
    const float* x  = (const float*)d_in[0];   // [B,S,D]
    const float* wq = (const float*)d_in[1];   // [D,U]
    const float* wk = (const float*)d_in[2];
    const float* wv = (const float*)d_in[3];

    float* out  = (float*)d_out;
    float* ctx  = out;                         // [B,S,U]
    float* attn = out + NX;                    // [B,S,S]

    cudaFuncSetAttribute(vmt_kernel,     cudaFuncAttributeMaxDynamicSharedMemorySize, SMEM_DYN);
    cudaFuncSetAttribute(p_kernel,       cudaFuncAttributeMaxDynamicSharedMemorySize, SMEM_DYN);
    cudaFuncSetAttribute(scores_kernel,  cudaFuncAttributeMaxDynamicSharedMemorySize, SMEM_DYN);
    cudaFuncSetAttribute(context_kernel, cudaFuncAttributeMaxDynamicSharedMemorySize, SMEM_DYN);

    // 1. splits: x, Wq, Wk (plain), Wv (transposed)
    split_x_kernel<<<(int)(NX / 4 / 256), 256>>>(x);
    splitW_kernel<<<dim3((int)(NW / 4 / 256), 2), 256>>>(wq, wk);
    wsplitT_kernel<<<dim3(UU / 32, DD / 32), dim3(32, 8)>>>(wv);

    // 2. V^T = (x @ Wv)^T  and  Mt = scale * Wk @ Wq^T  (one launch)
    vmt_kernel<<<dim3(528), 256, SMEM_DYN>>>();

    // 3. P = x @ Mt^T  [16384x512]
    p_kernel<<<dim3(4, 128), 256, SMEM_DYN>>>();

    // 4. scores = P @ x^T per batch (scale already folded into Mt)
    scores_kernel<<<dim3(16, 16, BB), 256, SMEM_DYN>>>(attn);

    // 5. softmax + bf16 hi/lo split of attn
    softmax_split_kernel<<<dim3(BB * SS), 256>>>(attn);

    // 6. context = attn @ V per batch
    context_kernel<<<dim3(4, 16, BB), 256, SMEM_DYN>>>(ctx);
}